// round 1
// baseline (speedup 1.0000x reference)
#include <cuda_runtime.h>
#include <math.h>

#define N_NODES 20000
#define N_EDGES 200000
#define E_TOT   (N_EDGES + N_NODES)
#define N_FEAT  2048
#define H1      512
#define H2      30

// ---------------- device scratch (static, allocation-free) ----------------
__device__ float g_xw1[(size_t)N_NODES * H1];
__device__ float g_h1 [(size_t)N_NODES * H1];
__device__ float g_xw3[(size_t)N_NODES * H1];
__device__ float g_h3 [(size_t)N_NODES * H1];
__device__ float g_a1s[N_NODES];
__device__ float g_a1d[N_NODES];
__device__ float g_m  [N_NODES];
__device__ float g_den[N_NODES];
__device__ float g_ew [E_TOT];
__device__ int   g_cnt [N_NODES];
__device__ int   g_fill[N_NODES];
__device__ int   g_rowptr[N_NODES + 1];
__device__ int   g_eids[E_TOT];
__device__ double g_loss;

// ---------------- init (must run every call: graph replays) ----------------
__global__ void init_kernel() {
    int i = blockIdx.x * blockDim.x + threadIdx.x;
    if (i < N_NODES) {
        g_m[i] = 0.0f;        // sigmoid(e) > 0, so 0 is a safe max-identity (int-bits compare)
        g_den[i] = 0.0f;
        g_cnt[i] = 0;
        g_fill[i] = 0;
    }
    if (i == 0) g_loss = 0.0;
}

// ---------------- GEMM1: g_xw1 = features @ W1  (NN, row-major) ------------
#define BM 128
#define BN 128
#define BK 8
#define TM 8
#define TN 8

__global__ __launch_bounds__(256) void sgemm1_kernel(
    const float* __restrict__ A,   // [N_NODES, N_FEAT]
    const float* __restrict__ B)   // [N_FEAT, H1]
{
    const int M = N_NODES, N = H1, K = N_FEAT;
    __shared__ float As[BK][BM];
    __shared__ float Bs[BK][BN];
    int tid  = threadIdx.x;
    int bm   = blockIdx.y * BM;
    int bn   = blockIdx.x * BN;
    int arow = tid >> 1;
    int acol = (tid & 1) * 4;
    int brow = tid >> 5;
    int bcol = (tid & 31) * 4;
    int tr   = (tid >> 4) * TM;
    int tc   = (tid & 15) * TN;
    float acc[TM][TN] = {};
    for (int k0 = 0; k0 < K; k0 += BK) {
        float4 av = make_float4(0.f, 0.f, 0.f, 0.f);
        if (bm + arow < M)
            av = *(const float4*)&A[(size_t)(bm + arow) * K + k0 + acol];
        As[acol + 0][arow] = av.x; As[acol + 1][arow] = av.y;
        As[acol + 2][arow] = av.z; As[acol + 3][arow] = av.w;
        float4 bv = *(const float4*)&B[(size_t)(k0 + brow) * N + bn + bcol];
        *(float4*)&Bs[brow][bcol] = bv;
        __syncthreads();
#pragma unroll
        for (int kk = 0; kk < BK; kk++) {
            float ra[TM], rb[TN];
#pragma unroll
            for (int i = 0; i < TM; i++) ra[i] = As[kk][tr + i];
#pragma unroll
            for (int j = 0; j < TN; j++) rb[j] = Bs[kk][tc + j];
#pragma unroll
            for (int i = 0; i < TM; i++)
#pragma unroll
                for (int j = 0; j < TN; j++)
                    acc[i][j] += ra[i] * rb[j];
        }
        __syncthreads();
    }
#pragma unroll
    for (int i = 0; i < TM; i++) {
        int row = bm + tr + i;
        if (row < M) {
#pragma unroll
            for (int j = 0; j < TN; j += 4)
                *(float4*)&g_xw1[(size_t)row * N + bn + tc + j] =
                    make_float4(acc[i][j], acc[i][j + 1], acc[i][j + 2], acc[i][j + 3]);
        }
    }
}

// ---------------- attention logits: a1s = xw1@att_src, a1d = xw1@att_dst ---
__global__ void att_kernel(const float* __restrict__ asrc,
                           const float* __restrict__ adst) {
    int gw   = (blockIdx.x * blockDim.x + threadIdx.x) >> 5;
    int lane = threadIdx.x & 31;
    if (gw >= N_NODES) return;
    const float* row = g_xw1 + (size_t)gw * H1;
    float s1 = 0.f, s2 = 0.f;
    for (int k = lane; k < H1; k += 32) {
        float v = row[k];
        s1 += v * asrc[k];
        s2 += v * adst[k];
    }
#pragma unroll
    for (int o = 16; o; o >>= 1) {
        s1 += __shfl_down_sync(0xffffffffu, s1, o);
        s2 += __shfl_down_sync(0xffffffffu, s2, o);
    }
    if (lane == 0) { g_a1s[gw] = s1; g_a1d[gw] = s2; }
}

// ---------------- edge pass 1: e = sigmoid(...), segment max, counts -------
__global__ void edge_pass1(const int* __restrict__ ei) {
    int e = blockIdx.x * blockDim.x + threadIdx.x;
    if (e >= E_TOT) return;
    int s, d;
    if (e < N_EDGES) { s = ei[e]; d = ei[N_EDGES + e]; }
    else             { s = d = e - N_EDGES; }
    float x = g_a1s[s] + g_a1d[d];
    float sig = 1.0f / (1.0f + expf(-x));
    g_ew[e] = sig;
    atomicMax((int*)&g_m[d], __float_as_int(sig));   // sig > 0: int compare valid
    atomicAdd(&g_cnt[d], 1);
}

// ---------------- edge pass 2: ex = exp(e - m[d]), segment sum -------------
__global__ void edge_pass2(const int* __restrict__ ei) {
    int e = blockIdx.x * blockDim.x + threadIdx.x;
    if (e >= E_TOT) return;
    int d = (e < N_EDGES) ? ei[N_EDGES + e] : (e - N_EDGES);
    float ex = expf(g_ew[e] - g_m[d]);
    g_ew[e] = ex;
    atomicAdd(&g_den[d], ex);
}

// ---------------- single-block exclusive scan over counts ------------------
__global__ void scan_kernel() {
    __shared__ int sh[1024];
    int tid = threadIdx.x;
    int carry = 0;
    for (int base = 0; base < N_NODES; base += 1024) {
        int i = base + tid;
        int v = (i < N_NODES) ? g_cnt[i] : 0;
        sh[tid] = v;
        __syncthreads();
        for (int off = 1; off < 1024; off <<= 1) {
            int t = (tid >= off) ? sh[tid - off] : 0;
            __syncthreads();
            sh[tid] += t;
            __syncthreads();
        }
        if (i < N_NODES) g_rowptr[i] = carry + sh[tid] - v;
        int tot = sh[1023];
        __syncthreads();
        carry += tot;
    }
    if (tid == 0) g_rowptr[N_NODES] = carry;
}

// ---------------- CSR fill --------------------------------------------------
__global__ void fill_kernel(const int* __restrict__ ei) {
    int e = blockIdx.x * blockDim.x + threadIdx.x;
    if (e >= E_TOT) return;
    int d = (e < N_EDGES) ? ei[N_EDGES + e] : (e - N_EDGES);
    int pos = atomicAdd(&g_fill[d], 1);
    g_eids[g_rowptr[d] + pos] = e;
}

// ---------------- gather-propagate + ELU (PASS 0: xw1->h1, 1: xw3->h3) -----
template <int PASS>
__global__ __launch_bounds__(128) void gather_kernel(const int* __restrict__ ei) {
    const float* __restrict__ X = (PASS == 0) ? g_xw1 : g_xw3;
    float* __restrict__ Y       = (PASS == 0) ? g_h1  : g_h3;
    int n   = blockIdx.x;
    int tid = threadIdx.x;   // 128 threads, 4 cols each
    int start = g_rowptr[n], end = g_rowptr[n + 1];
    float dinv = 1.0f / g_den[n];
    float a0 = 0.f, a1 = 0.f, a2 = 0.f, a3 = 0.f;
    for (int i = start; i < end; i++) {
        int eid = g_eids[i];
        int s = (eid < N_EDGES) ? ei[eid] : (eid - N_EDGES);
        float w = g_ew[eid] * dinv;
        const float* xr = X + (size_t)s * H1;
        a0 += w * xr[tid];
        a1 += w * xr[tid + 128];
        a2 += w * xr[tid + 256];
        a3 += w * xr[tid + 384];
    }
    float* yr = Y + (size_t)n * H1;
    yr[tid]       = (a0 > 0.f) ? a0 : expm1f(a0);
    yr[tid + 128] = (a1 > 0.f) ? a1 : expm1f(a1);
    yr[tid + 256] = (a2 > 0.f) ? a2 : expm1f(a2);
    yr[tid + 384] = (a3 > 0.f) ? a3 : expm1f(a3);
}

// ---------------- fused: h2 = norm(h1@W2); xw3 = h2@W2^T -------------------
__global__ void h2xw3_kernel(const float* __restrict__ W2) {
    int gw   = (blockIdx.x * blockDim.x + threadIdx.x) >> 5;
    int lane = threadIdx.x & 31;
    int w    = threadIdx.x >> 5;
    __shared__ float sh2[8][32];
    if (gw >= N_NODES) return;
    const float* h1r = g_h1 + (size_t)gw * H1;
    float hj = 0.f;
    if (lane < H2) {
#pragma unroll 4
        for (int k = 0; k < H1; k++)
            hj += h1r[k] * W2[k * H2 + lane];
    }
    float sq = (lane < H2) ? hj * hj : 0.f;
#pragma unroll
    for (int o = 16; o; o >>= 1) sq += __shfl_xor_sync(0xffffffffu, sq, o);
    float inv = 1.0f / fmaxf(sqrtf(sq), 1e-12f);
    hj *= inv;
    if (lane < H2) sh2[w][lane] = hj;
    __syncwarp();
    float* outp = g_xw3 + (size_t)gw * H1;
    for (int k = lane; k < H1; k += 32) {
        float a = 0.f;
#pragma unroll
        for (int j = 0; j < H2; j++)
            a += sh2[w][j] * W2[k * H2 + j];
        outp[k] = a;
    }
}

// ---------------- GEMM4 + fused MSE: loss += (features - h3@W1^T)^2 --------
__global__ __launch_bounds__(256) void sgemm4_loss_kernel(
    const float* __restrict__ W1t,  // W1 [N_FEAT, H1] used as B^T ([N,K])
    const float* __restrict__ F)    // features [N_NODES, N_FEAT]
{
    const int M = N_NODES, N = N_FEAT, K = H1;
    __shared__ float As[BK][BM];
    __shared__ float Bs[BK][BN];
    int tid  = threadIdx.x;
    int bm   = blockIdx.y * BM;
    int bn   = blockIdx.x * BN;
    int arow = tid >> 1;
    int acol = (tid & 1) * 4;
    int bnl  = tid >> 1;
    int bk   = (tid & 1) * 4;
    int tr   = (tid >> 4) * TM;
    int tc   = (tid & 15) * TN;
    float acc[TM][TN] = {};
    for (int k0 = 0; k0 < K; k0 += BK) {
        float4 av = make_float4(0.f, 0.f, 0.f, 0.f);
        if (bm + arow < M)
            av = *(const float4*)&g_h3[(size_t)(bm + arow) * K + k0 + acol];
        As[acol + 0][arow] = av.x; As[acol + 1][arow] = av.y;
        As[acol + 2][arow] = av.z; As[acol + 3][arow] = av.w;
        float4 bv = *(const float4*)&W1t[(size_t)(bn + bnl) * K + k0 + bk];
        Bs[bk + 0][bnl] = bv.x; Bs[bk + 1][bnl] = bv.y;
        Bs[bk + 2][bnl] = bv.z; Bs[bk + 3][bnl] = bv.w;
        __syncthreads();
#pragma unroll
        for (int kk = 0; kk < BK; kk++) {
            float ra[TM], rb[TN];
#pragma unroll
            for (int i = 0; i < TM; i++) ra[i] = As[kk][tr + i];
#pragma unroll
            for (int j = 0; j < TN; j++) rb[j] = Bs[kk][tc + j];
#pragma unroll
            for (int i = 0; i < TM; i++)
#pragma unroll
                for (int j = 0; j < TN; j++)
                    acc[i][j] += ra[i] * rb[j];
        }
        __syncthreads();
    }
    // fused MSE epilogue: never materialize h4
    float lsum = 0.f;
#pragma unroll
    for (int i = 0; i < TM; i++) {
        int row = bm + tr + i;
        if (row < M) {
#pragma unroll
            for (int j = 0; j < TN; j++) {
                float dlt = F[(size_t)row * N + bn + tc + j] - acc[i][j];
                lsum += dlt * dlt;
            }
        }
    }
    __shared__ float red[256];
    red[tid] = lsum;
    __syncthreads();
    for (int s = 128; s > 0; s >>= 1) {
        if (tid < s) red[tid] += red[tid + s];
        __syncthreads();
    }
    if (tid == 0) atomicAdd(&g_loss, (double)red[0]);
}

// ---------------- finalize --------------------------------------------------
__global__ void finalize_kernel(float* out) {
    out[0] = (float)(g_loss / ((double)N_NODES * (double)N_FEAT));
}

// ---------------- launch ----------------------------------------------------
extern "C" void kernel_launch(void* const* d_in, const int* in_sizes, int n_in,
                              void* d_out, int out_size) {
    const float* features = (const float*)d_in[0];
    const int*   edge_idx = (const int*)d_in[1];
    const float* W1       = (const float*)d_in[2];
    const float* att_src1 = (const float*)d_in[3];
    const float* att_dst1 = (const float*)d_in[4];
    const float* W2       = (const float*)d_in[5];
    float* out = (float*)d_out;

    init_kernel<<<(N_NODES + 255) / 256, 256>>>();

    dim3 g1(H1 / BN, (N_NODES + BM - 1) / BM);
    sgemm1_kernel<<<g1, 256>>>(features, W1);

    att_kernel<<<(N_NODES * 32 + 255) / 256, 256>>>(att_src1, att_dst1);

    int egrid = (E_TOT + 255) / 256;
    edge_pass1<<<egrid, 256>>>(edge_idx);
    edge_pass2<<<egrid, 256>>>(edge_idx);
    scan_kernel<<<1, 1024>>>();
    fill_kernel<<<egrid, 256>>>(edge_idx);

    gather_kernel<0><<<N_NODES, 128>>>(edge_idx);

    h2xw3_kernel<<<(N_NODES * 32 + 255) / 256, 256>>>(W2);

    gather_kernel<1><<<N_NODES, 128>>>(edge_idx);

    dim3 g4(N_FEAT / BN, (N_NODES + BM - 1) / BM);
    sgemm4_loss_kernel<<<g4, 256>>>(W1, features);

    finalize_kernel<<<1, 1>>>(out);
}

// round 3
// speedup vs baseline: 3.4299x; 3.4299x over previous
#include <cuda_runtime.h>
#include <math.h>
#include <stdint.h>

#define N_NODES 20000
#define N_EDGES 200000
#define E_TOT   (N_EDGES + N_NODES)
#define N_FEAT  2048
#define H1      512
#define H2      30

// ---------------- device scratch (static, allocation-free) ----------------
__device__ float g_xw1[(size_t)N_NODES * H1];
__device__ float g_h1 [(size_t)N_NODES * H1];
__device__ float g_xw3[(size_t)N_NODES * H1];
__device__ float g_h3 [(size_t)N_NODES * H1];
__device__ float g_w1t[(size_t)H1 * N_FEAT];     // W1^T  [512, 2048]
__device__ float g_a1s[N_NODES];
__device__ float g_a1d[N_NODES];
__device__ float g_m  [N_NODES];
__device__ float g_den[N_NODES];
__device__ float g_ew [E_TOT];
__device__ int   g_cnt [N_NODES];
__device__ int   g_fill[N_NODES];
__device__ int   g_rowptr[N_NODES + 1];
__device__ int   g_eids[E_TOT];
__device__ double g_loss;

// ---------------- helpers ---------------------------------------------------
__device__ __forceinline__ uint32_t f2tf32(float f) {
    uint32_t r;
    asm("cvt.rna.tf32.f32 %0, %1;" : "=r"(r) : "f"(f));
    return r;
}

__device__ __forceinline__ void mma_tf32(float* c, const uint32_t* a, const uint32_t* b) {
    asm volatile(
        "mma.sync.aligned.m16n8k8.row.col.f32.tf32.tf32.f32 "
        "{%0,%1,%2,%3}, {%4,%5,%6,%7}, {%8,%9}, {%0,%1,%2,%3};"
        : "+f"(c[0]), "+f"(c[1]), "+f"(c[2]), "+f"(c[3])
        : "r"(a[0]), "r"(a[1]), "r"(a[2]), "r"(a[3]), "r"(b[0]), "r"(b[1]));
}

// ---------------- init ------------------------------------------------------
__global__ void init_kernel() {
    int i = blockIdx.x * blockDim.x + threadIdx.x;
    if (i < N_NODES) {
        g_m[i] = 0.0f;
        g_den[i] = 0.0f;
        g_cnt[i] = 0;
        g_fill[i] = 0;
    }
    if (i == 0) g_loss = 0.0;
}

// ---------------- W1 transpose: g_w1t[n][k] = W1[k][n] ----------------------
__global__ void transpose_w1_kernel(const float* __restrict__ W1) {
    __shared__ float tile[32][33];
    int x = blockIdx.x * 32 + threadIdx.x;
    int y = blockIdx.y * 32 + threadIdx.y;
#pragma unroll
    for (int j = 0; j < 32; j += 8)
        tile[threadIdx.y + j][threadIdx.x] = W1[(size_t)(y + j) * H1 + x];
    __syncthreads();
    int xo = blockIdx.y * 32 + threadIdx.x;
    int yo = blockIdx.x * 32 + threadIdx.y;
#pragma unroll
    for (int j = 0; j < 32; j += 8)
        g_w1t[(size_t)(yo + j) * N_FEAT + xo] = tile[threadIdx.x][threadIdx.y + j];
}

// ---------------- tf32 mma.sync GEMM: C[128x128] = A[M,K] @ B[N,K]^T --------
// MODE 0: store C.   MODE 1: fused MSE vs F, no store.
#define SPAD 36   // smem row stride in floats (conflict-free fragment loads)

template <int MODE>
__global__ __launch_bounds__(256) void gemm_mma_kernel(
    const float* __restrict__ A, const float* __restrict__ B,
    const float* __restrict__ F, float* __restrict__ C,
    int M, int N, int K)
{
    __shared__ uint32_t sA[128 * SPAD];
    __shared__ uint32_t sB[128 * SPAD];

    const int tid  = threadIdx.x;
    const int lane = tid & 31;
    const int wid  = tid >> 5;
    const int wm   = (wid & 3) * 32;   // warp M offset in tile
    const int wn   = (wid >> 2) * 64;  // warp N offset in tile
    const int gid  = lane >> 2;        // 0..7
    const int tig  = lane & 3;         // 0..3
    const int bm   = blockIdx.y * 128;
    const int bn   = blockIdx.x * 128;

    float c[2][8][4];
#pragma unroll
    for (int mt = 0; mt < 2; mt++)
#pragma unroll
        for (int nt = 0; nt < 8; nt++)
#pragma unroll
            for (int q = 0; q < 4; q++) c[mt][nt][q] = 0.f;

    const int NC = K / 32;
    float4 pa[4], pb[4];
    // prefetch chunk 0
#pragma unroll
    for (int i = 0; i < 4; i++) {
        int f = tid + i * 256;
        int row = f >> 3, col = (f & 7) * 4;
        int am = bm + row;
        pa[i] = (am < M) ? *(const float4*)&A[(size_t)am * K + col]
                         : make_float4(0.f, 0.f, 0.f, 0.f);
        pb[i] = *(const float4*)&B[(size_t)(bn + row) * K + col];
    }

    for (int ch = 0; ch < NC; ch++) {
        // store current chunk (tf32-converted)
#pragma unroll
        for (int i = 0; i < 4; i++) {
            int f = tid + i * 256;
            int row = f >> 3, col = (f & 7) * 4;
            uint32_t* pA = &sA[row * SPAD + col];
            uint32_t* pB = &sB[row * SPAD + col];
            pA[0] = f2tf32(pa[i].x); pA[1] = f2tf32(pa[i].y);
            pA[2] = f2tf32(pa[i].z); pA[3] = f2tf32(pa[i].w);
            pB[0] = f2tf32(pb[i].x); pB[1] = f2tf32(pb[i].y);
            pB[2] = f2tf32(pb[i].z); pB[3] = f2tf32(pb[i].w);
        }
        __syncthreads();

        // prefetch next chunk (LDGs overlap with MMA below)
        if (ch + 1 < NC) {
            int k0 = (ch + 1) * 32;
#pragma unroll
            for (int i = 0; i < 4; i++) {
                int f = tid + i * 256;
                int row = f >> 3, col = (f & 7) * 4;
                int am = bm + row;
                pa[i] = (am < M) ? *(const float4*)&A[(size_t)am * K + k0 + col]
                                 : make_float4(0.f, 0.f, 0.f, 0.f);
                pb[i] = *(const float4*)&B[(size_t)(bn + row) * K + k0 + col];
            }
        }

        // compute: 4 k8-steps
#pragma unroll
        for (int ks = 0; ks < 4; ks++) {
            uint32_t afr[2][4];
#pragma unroll
            for (int mt = 0; mt < 2; mt++) {
                int base = (wm + mt * 16 + gid) * SPAD + ks * 8 + tig;
                afr[mt][0] = sA[base];
                afr[mt][1] = sA[base + 8 * SPAD];
                afr[mt][2] = sA[base + 4];
                afr[mt][3] = sA[base + 8 * SPAD + 4];
            }
            uint32_t bfr[8][2];
#pragma unroll
            for (int nt = 0; nt < 8; nt++) {
                int base = (wn + nt * 8 + gid) * SPAD + ks * 8 + tig;
                bfr[nt][0] = sB[base];
                bfr[nt][1] = sB[base + 4];
            }
#pragma unroll
            for (int mt = 0; mt < 2; mt++)
#pragma unroll
                for (int nt = 0; nt < 8; nt++)
                    mma_tf32(c[mt][nt], afr[mt], bfr[nt]);
        }
        __syncthreads();
    }

    // ---------------- epilogue ----------------
    if (MODE == 0) {
#pragma unroll
        for (int mt = 0; mt < 2; mt++) {
            int r0 = bm + wm + mt * 16 + gid;
            int r1 = r0 + 8;
#pragma unroll
            for (int nt = 0; nt < 8; nt++) {
                int col = bn + wn + nt * 8 + tig * 2;
                if (r0 < M)
                    *(float2*)&C[(size_t)r0 * N + col] = make_float2(c[mt][nt][0], c[mt][nt][1]);
                if (r1 < M)
                    *(float2*)&C[(size_t)r1 * N + col] = make_float2(c[mt][nt][2], c[mt][nt][3]);
            }
        }
    } else {
        float lsum = 0.f;
#pragma unroll
        for (int mt = 0; mt < 2; mt++) {
            int r0 = bm + wm + mt * 16 + gid;
            int r1 = r0 + 8;
#pragma unroll
            for (int nt = 0; nt < 8; nt++) {
                int col = bn + wn + nt * 8 + tig * 2;
                if (r0 < M) {
                    const float* fr = &F[(size_t)r0 * N + col];
                    float d0 = fr[0] - c[mt][nt][0];
                    float d1 = fr[1] - c[mt][nt][1];
                    lsum += d0 * d0 + d1 * d1;
                }
                if (r1 < M) {
                    const float* fr = &F[(size_t)r1 * N + col];
                    float d2 = fr[0] - c[mt][nt][2];
                    float d3 = fr[1] - c[mt][nt][3];
                    lsum += d2 * d2 + d3 * d3;
                }
            }
        }
#pragma unroll
        for (int o = 16; o; o >>= 1) lsum += __shfl_xor_sync(0xffffffffu, lsum, o);
        __shared__ float warp_s[8];
        if (lane == 0) warp_s[wid] = lsum;
        __syncthreads();
        if (tid == 0) {
            float t = 0.f;
#pragma unroll
            for (int w = 0; w < 8; w++) t += warp_s[w];
            atomicAdd(&g_loss, (double)t);
        }
    }
}

// ---------------- attention logits -----------------------------------------
__global__ void att_kernel(const float* __restrict__ asrc,
                           const float* __restrict__ adst) {
    int gw   = (blockIdx.x * blockDim.x + threadIdx.x) >> 5;
    int lane = threadIdx.x & 31;
    if (gw >= N_NODES) return;
    const float* row = g_xw1 + (size_t)gw * H1;
    float s1 = 0.f, s2 = 0.f;
    for (int k = lane; k < H1; k += 32) {
        float v = row[k];
        s1 += v * asrc[k];
        s2 += v * adst[k];
    }
#pragma unroll
    for (int o = 16; o; o >>= 1) {
        s1 += __shfl_down_sync(0xffffffffu, s1, o);
        s2 += __shfl_down_sync(0xffffffffu, s2, o);
    }
    if (lane == 0) { g_a1s[gw] = s1; g_a1d[gw] = s2; }
}

// ---------------- edge pass 1 -----------------------------------------------
__global__ void edge_pass1(const int* __restrict__ ei) {
    int e = blockIdx.x * blockDim.x + threadIdx.x;
    if (e >= E_TOT) return;
    int s, d;
    if (e < N_EDGES) { s = ei[e]; d = ei[N_EDGES + e]; }
    else             { s = d = e - N_EDGES; }
    float x = g_a1s[s] + g_a1d[d];
    float sig = 1.0f / (1.0f + expf(-x));
    g_ew[e] = sig;
    atomicMax((int*)&g_m[d], __float_as_int(sig));
    atomicAdd(&g_cnt[d], 1);
}

// ---------------- edge pass 2 -----------------------------------------------
__global__ void edge_pass2(const int* __restrict__ ei) {
    int e = blockIdx.x * blockDim.x + threadIdx.x;
    if (e >= E_TOT) return;
    int d = (e < N_EDGES) ? ei[N_EDGES + e] : (e - N_EDGES);
    float ex = expf(g_ew[e] - g_m[d]);
    g_ew[e] = ex;
    atomicAdd(&g_den[d], ex);
}

// ---------------- exclusive scan --------------------------------------------
__global__ void scan_kernel() {
    __shared__ int sh[1024];
    int tid = threadIdx.x;
    int carry = 0;
    for (int base = 0; base < N_NODES; base += 1024) {
        int i = base + tid;
        int v = (i < N_NODES) ? g_cnt[i] : 0;
        sh[tid] = v;
        __syncthreads();
        for (int off = 1; off < 1024; off <<= 1) {
            int t = (tid >= off) ? sh[tid - off] : 0;
            __syncthreads();
            sh[tid] += t;
            __syncthreads();
        }
        if (i < N_NODES) g_rowptr[i] = carry + sh[tid] - v;
        int tot = sh[1023];
        __syncthreads();
        carry += tot;
    }
    if (tid == 0) g_rowptr[N_NODES] = carry;
}

// ---------------- CSR fill --------------------------------------------------
__global__ void fill_kernel(const int* __restrict__ ei) {
    int e = blockIdx.x * blockDim.x + threadIdx.x;
    if (e >= E_TOT) return;
    int d = (e < N_EDGES) ? ei[N_EDGES + e] : (e - N_EDGES);
    int pos = atomicAdd(&g_fill[d], 1);
    g_eids[g_rowptr[d] + pos] = e;
}

// ---------------- gather-propagate + ELU ------------------------------------
template <int PASS>
__global__ __launch_bounds__(128) void gather_kernel(const int* __restrict__ ei) {
    const float* __restrict__ X = (PASS == 0) ? g_xw1 : g_xw3;
    float* __restrict__ Y       = (PASS == 0) ? g_h1  : g_h3;
    int n   = blockIdx.x;
    int tid = threadIdx.x;
    int start = g_rowptr[n], end = g_rowptr[n + 1];
    float dinv = 1.0f / g_den[n];
    float a0 = 0.f, a1 = 0.f, a2 = 0.f, a3 = 0.f;
    for (int i = start; i < end; i++) {
        int eid = g_eids[i];
        int s = (eid < N_EDGES) ? ei[eid] : (eid - N_EDGES);
        float w = g_ew[eid] * dinv;
        const float* xr = X + (size_t)s * H1;
        a0 += w * xr[tid];
        a1 += w * xr[tid + 128];
        a2 += w * xr[tid + 256];
        a3 += w * xr[tid + 384];
    }
    float* yr = Y + (size_t)n * H1;
    yr[tid]       = (a0 > 0.f) ? a0 : expm1f(a0);
    yr[tid + 128] = (a1 > 0.f) ? a1 : expm1f(a1);
    yr[tid + 256] = (a2 > 0.f) ? a2 : expm1f(a2);
    yr[tid + 384] = (a3 > 0.f) ? a3 : expm1f(a3);
}

// ---------------- fused: h2 = norm(h1@W2); xw3 = h2@W2^T --------------------
__global__ void h2xw3_kernel(const float* __restrict__ W2) {
    int gw   = (blockIdx.x * blockDim.x + threadIdx.x) >> 5;
    int lane = threadIdx.x & 31;
    int w    = threadIdx.x >> 5;
    __shared__ float sh2[8][32];
    if (gw >= N_NODES) return;
    const float* h1r = g_h1 + (size_t)gw * H1;
    float hj = 0.f;
    if (lane < H2) {
#pragma unroll 4
        for (int k = 0; k < H1; k++)
            hj += h1r[k] * W2[k * H2 + lane];
    }
    float sq = (lane < H2) ? hj * hj : 0.f;
#pragma unroll
    for (int o = 16; o; o >>= 1) sq += __shfl_xor_sync(0xffffffffu, sq, o);
    float inv = 1.0f / fmaxf(sqrtf(sq), 1e-12f);
    hj *= inv;
    if (lane < H2) sh2[w][lane] = hj;
    __syncwarp();
    float* outp = g_xw3 + (size_t)gw * H1;
    for (int k = lane; k < H1; k += 32) {
        float a = 0.f;
#pragma unroll
        for (int j = 0; j < H2; j++)
            a += sh2[w][j] * W2[k * H2 + j];
        outp[k] = a;
    }
}

// ---------------- finalize --------------------------------------------------
__global__ void finalize_kernel(float* out) {
    out[0] = (float)(g_loss / ((double)N_NODES * (double)N_FEAT));
}

// ---------------- launch ----------------------------------------------------
extern "C" void kernel_launch(void* const* d_in, const int* in_sizes, int n_in,
                              void* d_out, int out_size) {
    const float* features = (const float*)d_in[0];
    const int*   edge_idx = (const int*)d_in[1];
    const float* W1       = (const float*)d_in[2];
    const float* att_src1 = (const float*)d_in[3];
    const float* att_dst1 = (const float*)d_in[4];
    const float* W2       = (const float*)d_in[5];
    float* out = (float*)d_out;

    static float* w1t_ptr = nullptr;
    static float* h3_ptr  = nullptr;
    static float* xw1_ptr = nullptr;
    if (!w1t_ptr) cudaGetSymbolAddress((void**)&w1t_ptr, g_w1t);
    if (!h3_ptr)  cudaGetSymbolAddress((void**)&h3_ptr,  g_h3);
    if (!xw1_ptr) cudaGetSymbolAddress((void**)&xw1_ptr, g_xw1);

    init_kernel<<<(N_NODES + 255) / 256, 256>>>();

    transpose_w1_kernel<<<dim3(H1 / 32, N_FEAT / 32), dim3(32, 8)>>>(W1);

    // GEMM1: xw1 = features @ W1   (A=[20000,2048], B=W1^T [512,2048])
    gemm_mma_kernel<0><<<dim3(H1 / 128, (N_NODES + 127) / 128), 256>>>(
        features, w1t_ptr, nullptr, xw1_ptr, N_NODES, H1, N_FEAT);

    att_kernel<<<(N_NODES * 32 + 255) / 256, 256>>>(att_src1, att_dst1);

    int egrid = (E_TOT + 255) / 256;
    edge_pass1<<<egrid, 256>>>(edge_idx);
    edge_pass2<<<egrid, 256>>>(edge_idx);
    scan_kernel<<<1, 1024>>>();
    fill_kernel<<<egrid, 256>>>(edge_idx);

    gather_kernel<0><<<N_NODES, 128>>>(edge_idx);

    h2xw3_kernel<<<(N_NODES * 32 + 255) / 256, 256>>>(W2);

    gather_kernel<1><<<N_NODES, 128>>>(edge_idx);

    // GEMM4 + fused MSE: loss = sum((features - h3 @ W1^T)^2)
    gemm_mma_kernel<1><<<dim3(N_FEAT / 128, (N_NODES + 127) / 128), 256>>>(
        h3_ptr, W1, features, nullptr, N_NODES, N_FEAT, H1);

    finalize_kernel<<<1, 1>>>(out);
}

// round 4
// speedup vs baseline: 4.9657x; 1.4478x over previous
#include <cuda_runtime.h>
#include <cuda_bf16.h>
#include <math.h>
#include <stdint.h>

#define N_NODES 20000
#define N_EDGES 200000
#define E_TOT   (N_EDGES + N_NODES)
#define N_FEAT  2048
#define H1      512
#define H2      30

// ---------------- device scratch (static, allocation-free) ----------------
__device__ __nv_bfloat16 g_xw1b[(size_t)N_NODES * H1];
__device__ __nv_bfloat16 g_xw3b[(size_t)N_NODES * H1];
__device__ float g_h1 [(size_t)N_NODES * H1];
__device__ float g_h3 [(size_t)N_NODES * H1];
__device__ float g_w1t[(size_t)H1 * N_FEAT];     // W1^T  [512, 2048]
__device__ float g_a1s[N_NODES];
__device__ float g_a1d[N_NODES];
__device__ float g_den[N_NODES];
__device__ float g_ew [E_TOT];
__device__ int   g_cnt [N_NODES];
__device__ int   g_fill[N_NODES];
__device__ int   g_rowptr[N_NODES + 1];
__device__ int   g_srcid[E_TOT];
__device__ float g_wn  [E_TOT];
__device__ double g_loss;

// ---------------- helpers ---------------------------------------------------
__device__ __forceinline__ uint32_t pack_bf16x2(float lo, float hi) {
    uint32_t r;
    asm("cvt.rn.bf16x2.f32 %0, %1, %2;" : "=r"(r) : "f"(hi), "f"(lo));
    return r;
}
__device__ __forceinline__ float bf_lo(uint32_t u) { return __uint_as_float(u << 16); }
__device__ __forceinline__ float bf_hi(uint32_t u) { return __uint_as_float(u & 0xffff0000u); }

__device__ __forceinline__ void mma_bf16(float* c, const uint32_t* a, const uint32_t* b) {
    asm volatile(
        "mma.sync.aligned.m16n8k16.row.col.f32.bf16.bf16.f32 "
        "{%0,%1,%2,%3}, {%4,%5,%6,%7}, {%8,%9}, {%0,%1,%2,%3};"
        : "+f"(c[0]), "+f"(c[1]), "+f"(c[2]), "+f"(c[3])
        : "r"(a[0]), "r"(a[1]), "r"(a[2]), "r"(a[3]), "r"(b[0]), "r"(b[1]));
}

// ---------------- init ------------------------------------------------------
__global__ void init_kernel() {
    int i = blockIdx.x * blockDim.x + threadIdx.x;
    if (i < N_NODES) {
        g_den[i] = 0.0f;
        g_cnt[i] = 0;
        g_fill[i] = 0;
        g_a1s[i] = 0.0f;
        g_a1d[i] = 0.0f;
    }
    if (i == 0) g_loss = 0.0;
}

// ---------------- W1 transpose: g_w1t[n][k] = W1[k][n] ----------------------
__global__ void transpose_w1_kernel(const float* __restrict__ W1) {
    __shared__ float tile[32][33];
    int x = blockIdx.x * 32 + threadIdx.x;
    int y = blockIdx.y * 32 + threadIdx.y;
#pragma unroll
    for (int j = 0; j < 32; j += 8)
        tile[threadIdx.y + j][threadIdx.x] = W1[(size_t)(y + j) * H1 + x];
    __syncthreads();
    int xo = blockIdx.y * 32 + threadIdx.x;
    int yo = blockIdx.x * 32 + threadIdx.y;
#pragma unroll
    for (int j = 0; j < 32; j += 8)
        g_w1t[(size_t)(yo + j) * N_FEAT + xo] = tile[threadIdx.x][threadIdx.y + j];
}

// ---------------- bf16 mma GEMM: C[128x128] = A[M,K] @ B[N,K]^T -------------
// MODE 0: store bf16 C to g_xw1b + fused attention logits (atomicAdd a1s/a1d).
// MODE 1: fused MSE vs F, nothing stored.
#define SPADB 20   // uint32 (bf16x2 pair) row stride: 16 pairs + 4 pad (conflict-free)

template <int MODE>
__global__ __launch_bounds__(256) void gemm_bf16_kernel(
    const float* __restrict__ A, const float* __restrict__ B,
    const float* __restrict__ F,
    const float* __restrict__ asrc, const float* __restrict__ adst,
    int M, int N, int K)
{
    __shared__ uint32_t sA[2][128 * SPADB];
    __shared__ uint32_t sB[2][128 * SPADB];

    const int tid  = threadIdx.x;
    const int lane = tid & 31;
    const int wid  = tid >> 5;
    const int wm   = (wid & 3) * 32;
    const int wn   = (wid >> 2) * 64;
    const int gid  = lane >> 2;
    const int tig  = lane & 3;
    const int bm   = blockIdx.y * 128;
    const int bn   = blockIdx.x * 128;

    float c[2][8][4];
#pragma unroll
    for (int mt = 0; mt < 2; mt++)
#pragma unroll
        for (int nt = 0; nt < 8; nt++)
#pragma unroll
            for (int q = 0; q < 4; q++) c[mt][nt][q] = 0.f;

    const int NC = K / 32;
    float4 pa[4], pb[4];

    // prefetch + store chunk 0
#pragma unroll
    for (int i = 0; i < 4; i++) {
        int f = tid + i * 256;
        int row = f >> 3, col = (f & 7) * 4;
        int am = bm + row;
        pa[i] = (am < M) ? *(const float4*)&A[(size_t)am * K + col]
                         : make_float4(0.f, 0.f, 0.f, 0.f);
        pb[i] = *(const float4*)&B[(size_t)(bn + row) * K + col];
    }
#pragma unroll
    for (int i = 0; i < 4; i++) {
        int f = tid + i * 256;
        int row = f >> 3, cp = (f & 7) * 2;
        sA[0][row * SPADB + cp]     = pack_bf16x2(pa[i].x, pa[i].y);
        sA[0][row * SPADB + cp + 1] = pack_bf16x2(pa[i].z, pa[i].w);
        sB[0][row * SPADB + cp]     = pack_bf16x2(pb[i].x, pb[i].y);
        sB[0][row * SPADB + cp + 1] = pack_bf16x2(pb[i].z, pb[i].w);
    }
    __syncthreads();

    for (int ch = 0; ch < NC; ch++) {
        int p = ch & 1;
        // prefetch next chunk (LDG overlaps MMA)
        if (ch + 1 < NC) {
            int k0 = (ch + 1) * 32;
#pragma unroll
            for (int i = 0; i < 4; i++) {
                int f = tid + i * 256;
                int row = f >> 3, col = (f & 7) * 4;
                int am = bm + row;
                pa[i] = (am < M) ? *(const float4*)&A[(size_t)am * K + k0 + col]
                                 : make_float4(0.f, 0.f, 0.f, 0.f);
                pb[i] = *(const float4*)&B[(size_t)(bn + row) * K + k0 + col];
            }
        }
        // compute this chunk: 2 k16-steps
#pragma unroll
        for (int ks = 0; ks < 2; ks++) {
            uint32_t afr[2][4];
#pragma unroll
            for (int mt = 0; mt < 2; mt++) {
                int base = (wm + mt * 16 + gid) * SPADB + ks * 8 + tig;
                afr[mt][0] = sA[p][base];
                afr[mt][1] = sA[p][base + 8 * SPADB];
                afr[mt][2] = sA[p][base + 4];
                afr[mt][3] = sA[p][base + 8 * SPADB + 4];
            }
            uint32_t bfr[8][2];
#pragma unroll
            for (int nt = 0; nt < 8; nt++) {
                int base = (wn + nt * 8 + gid) * SPADB + ks * 8 + tig;
                bfr[nt][0] = sB[p][base];
                bfr[nt][1] = sB[p][base + 4];
            }
#pragma unroll
            for (int mt = 0; mt < 2; mt++)
#pragma unroll
                for (int nt = 0; nt < 8; nt++)
                    mma_bf16(c[mt][nt], afr[mt], bfr[nt]);
        }
        // store next chunk into the other buffer (no sync needed before: different buffer)
        if (ch + 1 < NC) {
#pragma unroll
            for (int i = 0; i < 4; i++) {
                int f = tid + i * 256;
                int row = f >> 3, cp = (f & 7) * 2;
                sA[p ^ 1][row * SPADB + cp]     = pack_bf16x2(pa[i].x, pa[i].y);
                sA[p ^ 1][row * SPADB + cp + 1] = pack_bf16x2(pa[i].z, pa[i].w);
                sB[p ^ 1][row * SPADB + cp]     = pack_bf16x2(pb[i].x, pb[i].y);
                sB[p ^ 1][row * SPADB + cp + 1] = pack_bf16x2(pb[i].z, pb[i].w);
            }
        }
        __syncthreads();
    }

    // ---------------- epilogue ----------------
    if (MODE == 0) {
        uint32_t* outb = (uint32_t*)g_xw1b;
        float ps[2][2] = {}, pd[2][2] = {};   // att partials [mt][half]
#pragma unroll
        for (int mt = 0; mt < 2; mt++) {
            int r0 = bm + wm + mt * 16 + gid;
            int r1 = r0 + 8;
#pragma unroll
            for (int nt = 0; nt < 8; nt++) {
                int col = bn + wn + nt * 8 + tig * 2;
                float s0 = asrc[col], s1 = asrc[col + 1];
                float d0 = adst[col], d1 = adst[col + 1];
                float c0 = c[mt][nt][0], c1 = c[mt][nt][1];
                float c2 = c[mt][nt][2], c3 = c[mt][nt][3];
                if (r0 < M) outb[((size_t)r0 * N + col) >> 1] = pack_bf16x2(c0, c1);
                if (r1 < M) outb[((size_t)r1 * N + col) >> 1] = pack_bf16x2(c2, c3);
                ps[mt][0] += c0 * s0 + c1 * s1;  pd[mt][0] += c0 * d0 + c1 * d1;
                ps[mt][1] += c2 * s0 + c3 * s1;  pd[mt][1] += c2 * d0 + c3 * d1;
            }
        }
        // reduce across the 4 lanes of each quad (tig)
#pragma unroll
        for (int o = 1; o <= 2; o <<= 1) {
#pragma unroll
            for (int mt = 0; mt < 2; mt++)
#pragma unroll
                for (int h = 0; h < 2; h++) {
                    ps[mt][h] += __shfl_xor_sync(0xffffffffu, ps[mt][h], o);
                    pd[mt][h] += __shfl_xor_sync(0xffffffffu, pd[mt][h], o);
                }
        }
        if (tig == 0) {
#pragma unroll
            for (int mt = 0; mt < 2; mt++)
#pragma unroll
                for (int h = 0; h < 2; h++) {
                    int r = bm + wm + mt * 16 + gid + h * 8;
                    if (r < M) {
                        atomicAdd(&g_a1s[r], ps[mt][h]);
                        atomicAdd(&g_a1d[r], pd[mt][h]);
                    }
                }
        }
    } else {
        float lsum = 0.f;
#pragma unroll
        for (int mt = 0; mt < 2; mt++) {
            int r0 = bm + wm + mt * 16 + gid;
            int r1 = r0 + 8;
#pragma unroll
            for (int nt = 0; nt < 8; nt++) {
                int col = bn + wn + nt * 8 + tig * 2;
                if (r0 < M) {
                    const float* fr = &F[(size_t)r0 * N + col];
                    float d0 = fr[0] - c[mt][nt][0];
                    float d1 = fr[1] - c[mt][nt][1];
                    lsum += d0 * d0 + d1 * d1;
                }
                if (r1 < M) {
                    const float* fr = &F[(size_t)r1 * N + col];
                    float d2 = fr[0] - c[mt][nt][2];
                    float d3 = fr[1] - c[mt][nt][3];
                    lsum += d2 * d2 + d3 * d3;
                }
            }
        }
#pragma unroll
        for (int o = 16; o; o >>= 1) lsum += __shfl_xor_sync(0xffffffffu, lsum, o);
        __shared__ float warp_s[8];
        if (lane == 0) warp_s[wid] = lsum;
        __syncthreads();
        if (tid == 0) {
            float t = 0.f;
#pragma unroll
            for (int w = 0; w < 8; w++) t += warp_s[w];
            atomicAdd(&g_loss, (double)t);
        }
    }
}

// ---------------- single edge pass: e=sigmoid, ew=exp(e) (no max needed) ----
// sigmoid output is in (0,1) so exp never overflows; softmax is shift-invariant.
__global__ void edge_pass(const int* __restrict__ ei) {
    int e = blockIdx.x * blockDim.x + threadIdx.x;
    if (e >= E_TOT) return;
    int s, d;
    if (e < N_EDGES) { s = ei[e]; d = ei[N_EDGES + e]; }
    else             { s = d = e - N_EDGES; }
    float x = g_a1s[s] + g_a1d[d];
    float sig = 1.0f / (1.0f + expf(-x));
    float ex = expf(sig);
    g_ew[e] = ex;
    atomicAdd(&g_den[d], ex);
    atomicAdd(&g_cnt[d], 1);
}

// ---------------- exclusive scan --------------------------------------------
__global__ void scan_kernel() {
    __shared__ int sh[1024];
    int tid = threadIdx.x;
    int carry = 0;
    for (int base = 0; base < N_NODES; base += 1024) {
        int i = base + tid;
        int v = (i < N_NODES) ? g_cnt[i] : 0;
        sh[tid] = v;
        __syncthreads();
        for (int off = 1; off < 1024; off <<= 1) {
            int t = (tid >= off) ? sh[tid - off] : 0;
            __syncthreads();
            sh[tid] += t;
            __syncthreads();
        }
        if (i < N_NODES) g_rowptr[i] = carry + sh[tid] - v;
        int tot = sh[1023];
        __syncthreads();
        carry += tot;
    }
    if (tid == 0) g_rowptr[N_NODES] = carry;
}

// ---------------- CSR fill: pre-resolve src + normalized weight -------------
__global__ void fill_kernel(const int* __restrict__ ei) {
    int e = blockIdx.x * blockDim.x + threadIdx.x;
    if (e >= E_TOT) return;
    int s, d;
    if (e < N_EDGES) { s = ei[e]; d = ei[N_EDGES + e]; }
    else             { s = d = e - N_EDGES; }
    int pos = atomicAdd(&g_fill[d], 1);
    int idx = g_rowptr[d] + pos;
    g_srcid[idx] = s;
    g_wn[idx] = g_ew[e] / g_den[d];
}

// ---------------- gather-propagate + ELU (bf16 in, fp32 out) ----------------
// warp per node; lane covers 16 cols (4 segs x 4 contiguous cols via bf16x2 pairs)
template <int PASS>
__global__ __launch_bounds__(256) void gather_kernel() {
    const uint32_t* __restrict__ X =
        (const uint32_t*)((PASS == 0) ? g_xw1b : g_xw3b);
    float* __restrict__ Y = (PASS == 0) ? g_h1 : g_h3;
    int gw = (blockIdx.x * blockDim.x + threadIdx.x) >> 5;
    if (gw >= N_NODES) return;
    int lane = threadIdx.x & 31;
    int start = g_rowptr[gw], end = g_rowptr[gw + 1];

    float acc[16];
#pragma unroll
    for (int q = 0; q < 16; q++) acc[q] = 0.f;

    for (int i = start; i < end; i++) {
        int s = g_srcid[i];
        float w = g_wn[i];
        const uint32_t* row = X + (size_t)s * (H1 / 2) + lane * 2;
#pragma unroll
        for (int seg = 0; seg < 4; seg++) {
            uint2 v = *(const uint2*)(row + seg * 64);
            acc[seg * 4 + 0] += w * bf_lo(v.x);
            acc[seg * 4 + 1] += w * bf_hi(v.x);
            acc[seg * 4 + 2] += w * bf_lo(v.y);
            acc[seg * 4 + 3] += w * bf_hi(v.y);
        }
    }
    float* yr = Y + (size_t)gw * H1 + lane * 4;
#pragma unroll
    for (int seg = 0; seg < 4; seg++) {
        float a0 = acc[seg * 4 + 0], a1 = acc[seg * 4 + 1];
        float a2 = acc[seg * 4 + 2], a3 = acc[seg * 4 + 3];
        *(float4*)(yr + seg * 128) = make_float4(
            (a0 > 0.f) ? a0 : expm1f(a0), (a1 > 0.f) ? a1 : expm1f(a1),
            (a2 > 0.f) ? a2 : expm1f(a2), (a3 > 0.f) ? a3 : expm1f(a3));
    }
}

// ---------------- fused: h2 = norm(h1@W2); xw3b = bf16(h2@W2^T) -------------
__global__ void h2xw3_kernel(const float* __restrict__ W2) {
    int gw   = (blockIdx.x * blockDim.x + threadIdx.x) >> 5;
    int lane = threadIdx.x & 31;
    int w    = threadIdx.x >> 5;
    __shared__ float sh2[8][32];
    if (gw >= N_NODES) return;
    const float* h1r = g_h1 + (size_t)gw * H1;
    float hj0 = 0.f, hj1 = 0.f;
    if (lane < H2) {
#pragma unroll 4
        for (int k = 0; k < H1; k += 2) {
            hj0 += h1r[k]     * W2[k * H2 + lane];
            hj1 += h1r[k + 1] * W2[(k + 1) * H2 + lane];
        }
    }
    float hj = hj0 + hj1;
    float sq = (lane < H2) ? hj * hj : 0.f;
#pragma unroll
    for (int o = 16; o; o >>= 1) sq += __shfl_xor_sync(0xffffffffu, sq, o);
    float inv = 1.0f / fmaxf(sqrtf(sq), 1e-12f);
    hj *= inv;
    if (lane < H2) sh2[w][lane] = hj;
    __syncwarp();
    __nv_bfloat16* outp = g_xw3b + (size_t)gw * H1;
    for (int k = lane; k < H1; k += 32) {
        float a = 0.f;
#pragma unroll
        for (int j = 0; j < H2; j++)
            a += sh2[w][j] * W2[k * H2 + j];
        outp[k] = __float2bfloat16(a);
    }
}

// ---------------- finalize --------------------------------------------------
__global__ void finalize_kernel(float* out) {
    out[0] = (float)(g_loss / ((double)N_NODES * (double)N_FEAT));
}

// ---------------- launch ----------------------------------------------------
extern "C" void kernel_launch(void* const* d_in, const int* in_sizes, int n_in,
                              void* d_out, int out_size) {
    const float* features = (const float*)d_in[0];
    const int*   edge_idx = (const int*)d_in[1];
    const float* W1       = (const float*)d_in[2];
    const float* att_src1 = (const float*)d_in[3];
    const float* att_dst1 = (const float*)d_in[4];
    const float* W2       = (const float*)d_in[5];
    float* out = (float*)d_out;

    static float* w1t_ptr = nullptr;
    static float* h3_ptr  = nullptr;
    if (!w1t_ptr) cudaGetSymbolAddress((void**)&w1t_ptr, g_w1t);
    if (!h3_ptr)  cudaGetSymbolAddress((void**)&h3_ptr,  g_h3);

    init_kernel<<<(N_NODES + 255) / 256, 256>>>();

    transpose_w1_kernel<<<dim3(H1 / 32, N_FEAT / 32), dim3(32, 8)>>>(W1);

    // GEMM1: xw1b = bf16(features @ W1) + fused attention logits
    gemm_bf16_kernel<0><<<dim3(H1 / 128, (N_NODES + 127) / 128), 256>>>(
        features, w1t_ptr, nullptr, att_src1, att_dst1, N_NODES, H1, N_FEAT);

    int egrid = (E_TOT + 255) / 256;
    edge_pass<<<egrid, 256>>>(edge_idx);
    scan_kernel<<<1, 1024>>>();
    fill_kernel<<<egrid, 256>>>(edge_idx);

    gather_kernel<0><<<(N_NODES * 32 + 255) / 256, 256>>>();

    h2xw3_kernel<<<(N_NODES * 32 + 255) / 256, 256>>>(W2);

    gather_kernel<1><<<(N_NODES * 32 + 255) / 256, 256>>>();

    // GEMM4 + fused MSE: loss = sum((features - h3 @ W1^T)^2)
    gemm_bf16_kernel<1><<<dim3(N_FEAT / 128, (N_NODES + 127) / 128), 256>>>(
        h3_ptr, W1, features, nullptr, nullptr, N_NODES, N_FEAT, H1);

    finalize_kernel<<<1, 1>>>(out);
}

// round 5
// speedup vs baseline: 5.7597x; 1.1599x over previous
#include <cuda_runtime.h>
#include <cuda_bf16.h>
#include <math.h>
#include <stdint.h>

#define N_NODES 20000
#define N_EDGES 200000
#define E_TOT   (N_EDGES + N_NODES)
#define N_FEAT  2048
#define H1      512
#define H2      30

// ---------------- device scratch (static, allocation-free) ----------------
__device__ __nv_bfloat16 g_featb[(size_t)N_NODES * N_FEAT]; // bf16 features
__device__ __nv_bfloat16 g_w1tb[(size_t)H1 * N_FEAT];       // bf16 W1^T [512,2048]
__device__ __nv_bfloat16 g_w1b [(size_t)N_FEAT * H1];       // bf16 W1   [2048,512]
__device__ __nv_bfloat16 g_xw1b[(size_t)N_NODES * H1];
__device__ __nv_bfloat16 g_xw3b[(size_t)N_NODES * H1];
__device__ __nv_bfloat16 g_h3b [(size_t)N_NODES * H1];
__device__ float g_h1 [(size_t)N_NODES * H1];
__device__ float g_a1s[N_NODES];
__device__ float g_a1d[N_NODES];
__device__ float g_den[N_NODES];
__device__ float g_ew [E_TOT];
__device__ int   g_cnt [N_NODES];
__device__ int   g_fill[N_NODES];
__device__ int   g_rowptr[N_NODES + 1];
__device__ int   g_srcid[E_TOT];
__device__ float g_wn  [E_TOT];
__device__ double g_loss;

// ---------------- helpers ---------------------------------------------------
__device__ __forceinline__ uint32_t pack_bf16x2(float lo, float hi) {
    uint32_t r;
    asm("cvt.rn.bf16x2.f32 %0, %1, %2;" : "=r"(r) : "f"(hi), "f"(lo));
    return r;
}
__device__ __forceinline__ float bf_lo(uint32_t u) { return __uint_as_float(u << 16); }
__device__ __forceinline__ float bf_hi(uint32_t u) { return __uint_as_float(u & 0xffff0000u); }

__device__ __forceinline__ void mma_bf16(float* c, const uint32_t* a, const uint32_t* b) {
    asm volatile(
        "mma.sync.aligned.m16n8k16.row.col.f32.bf16.bf16.f32 "
        "{%0,%1,%2,%3}, {%4,%5,%6,%7}, {%8,%9}, {%0,%1,%2,%3};"
        : "+f"(c[0]), "+f"(c[1]), "+f"(c[2]), "+f"(c[3])
        : "r"(a[0]), "r"(a[1]), "r"(a[2]), "r"(a[3]), "r"(b[0]), "r"(b[1]));
}
__device__ __forceinline__ void ldsm4(uint32_t* r, uint32_t a) {
    asm volatile("ldmatrix.sync.aligned.m8n8.x4.shared.b16 {%0,%1,%2,%3}, [%4];"
        : "=r"(r[0]), "=r"(r[1]), "=r"(r[2]), "=r"(r[3]) : "r"(a));
}
__device__ __forceinline__ void cp16(uint32_t dst, const void* src, int sz) {
    asm volatile("cp.async.cg.shared.global [%0], [%1], 16, %2;"
        :: "r"(dst), "l"(src), "r"(sz));
}
#define CP_COMMIT() asm volatile("cp.async.commit_group;" ::: "memory")
#define CP_WAIT1()  asm volatile("cp.async.wait_group 1;" ::: "memory")

// ---------------- init ------------------------------------------------------
__global__ void init_kernel() {
    int i = blockIdx.x * blockDim.x + threadIdx.x;
    if (i < N_NODES) {
        g_den[i] = 0.0f;
        g_cnt[i] = 0;
        g_fill[i] = 0;
        g_a1s[i] = 0.0f;
        g_a1d[i] = 0.0f;
    }
    if (i == 0) g_loss = 0.0;
}

// ---------------- converts --------------------------------------------------
__global__ void convert_feat_kernel(const float* __restrict__ F) {
    size_t i = (size_t)blockIdx.x * blockDim.x + threadIdx.x;   // float4 index
    size_t n4 = (size_t)N_NODES * N_FEAT / 4;
    uint2* out = (uint2*)g_featb;
    for (; i < n4; i += (size_t)gridDim.x * blockDim.x) {
        float4 v = ((const float4*)F)[i];
        out[i] = make_uint2(pack_bf16x2(v.x, v.y), pack_bf16x2(v.z, v.w));
    }
}
__global__ void convert_w1_kernel(const float* __restrict__ W1) {
    size_t i = (size_t)blockIdx.x * blockDim.x + threadIdx.x;
    size_t n4 = (size_t)N_FEAT * H1 / 4;
    uint2* out = (uint2*)g_w1b;
    if (i < n4) {
        float4 v = ((const float4*)W1)[i];
        out[i] = make_uint2(pack_bf16x2(v.x, v.y), pack_bf16x2(v.z, v.w));
    }
}
__global__ void transpose_w1_kernel(const float* __restrict__ W1) {
    __shared__ float tile[32][33];
    int x = blockIdx.x * 32 + threadIdx.x;
    int y = blockIdx.y * 32 + threadIdx.y;
#pragma unroll
    for (int j = 0; j < 32; j += 8)
        tile[threadIdx.y + j][threadIdx.x] = W1[(size_t)(y + j) * H1 + x];
    __syncthreads();
    int xo = blockIdx.y * 32 + threadIdx.x;
    int yo = blockIdx.x * 32 + threadIdx.y;
#pragma unroll
    for (int j = 0; j < 32; j += 8)
        g_w1tb[(size_t)(yo + j) * N_FEAT + xo] = __float2bfloat16(tile[threadIdx.x][threadIdx.y + j]);
}

// ---------------- bf16 GEMM (cp.async + ldmatrix): C = A[M,K] @ B[N,K]^T ----
// MODE 0: store bf16 C to g_xw1b + fused attention logits.
// MODE 1: fused MSE vs F, nothing stored.
// SMEM tile: 128 rows x 64B data (k32 bf16) + 16B pad = 80B stride, 10240B/matrix.
#define ROWB  80
#define TILEB 10240
#define BUFB  (2 * TILEB)

template <int MODE>
__global__ __launch_bounds__(256, 2) void gemm_bf16_kernel(
    const __nv_bfloat16* __restrict__ A, const __nv_bfloat16* __restrict__ B,
    const float* __restrict__ F,
    const float* __restrict__ asrc, const float* __restrict__ adst,
    int M, int N, int K)
{
    __shared__ __align__(128) char smem[2][BUFB];   // [buf][A | B]

    const int tid  = threadIdx.x;
    const int lane = tid & 31;
    const int wid  = tid >> 5;
    const int wm   = (wid & 3) * 32;
    const int wn   = (wid >> 2) * 64;
    const int bm   = blockIdx.y * 128;
    const int bn   = blockIdx.x * 128;

    uint32_t smem_base;
    asm("{ .reg .u64 t; cvta.to.shared.u64 t, %1; cvt.u32.u64 %0, t; }"
        : "=r"(smem_base) : "l"((void*)smem));

    float c[2][8][4];
#pragma unroll
    for (int mt = 0; mt < 2; mt++)
#pragma unroll
        for (int nt = 0; nt < 8; nt++)
#pragma unroll
            for (int q = 0; q < 4; q++) c[mt][nt][q] = 0.f;

    const int NC = K / 32;

    // per-thread cp.async coords: 512 16B-ops per matrix, 2 per thread
    const int r0c = tid >> 2, s0 = (tid & 3);           // row 0..63, seg
    const int r1c = r0c + 64;
    // per-lane ldmatrix offsets (byte offsets within a matrix tile)
    uint32_t aoff[2], boff[4];
#pragma unroll
    for (int mt = 0; mt < 2; mt++)
        aoff[mt] = (uint32_t)((wm + mt * 16 + (lane & 15)) * ROWB + (lane >> 4) * 16);
#pragma unroll
    for (int q = 0; q < 4; q++)
        boff[q] = (uint32_t)((wn + q * 16 + (lane & 7) + ((lane >> 4) << 3)) * ROWB
                             + ((lane >> 3) & 1) * 16);

    auto issue = [&](int p, int ch) {
        uint32_t ab = smem_base + p * BUFB;
        uint32_t bb = ab + TILEB;
        int k0 = ch * 32;
        int am0 = bm + r0c, am1 = bm + r1c;
        cp16(ab + r0c * ROWB + s0 * 16, A + (size_t)am0 * K + k0 + s0 * 8, am0 < M ? 16 : 0);
        cp16(ab + r1c * ROWB + s0 * 16, A + (size_t)am1 * K + k0 + s0 * 8, am1 < M ? 16 : 0);
        cp16(bb + r0c * ROWB + s0 * 16, B + (size_t)(bn + r0c) * K + k0 + s0 * 8, 16);
        cp16(bb + r1c * ROWB + s0 * 16, B + (size_t)(bn + r1c) * K + k0 + s0 * 8, 16);
    };

    issue(0, 0); CP_COMMIT();
    issue(1, 1); CP_COMMIT();

    for (int ch = 0; ch < NC; ch++) {
        int p = ch & 1;
        CP_WAIT1();
        __syncthreads();
        uint32_t ab = smem_base + p * BUFB;
        uint32_t bb = ab + TILEB;
#pragma unroll
        for (int ks = 0; ks < 2; ks++) {
            uint32_t afr[2][4];
#pragma unroll
            for (int mt = 0; mt < 2; mt++)
                ldsm4(afr[mt], ab + aoff[mt] + ks * 32);
            uint32_t bfr[4][4];
#pragma unroll
            for (int q = 0; q < 4; q++)
                ldsm4(bfr[q], bb + boff[q] + ks * 32);
#pragma unroll
            for (int mt = 0; mt < 2; mt++)
#pragma unroll
                for (int q = 0; q < 4; q++) {
                    mma_bf16(c[mt][2 * q],     afr[mt], &bfr[q][0]);
                    mma_bf16(c[mt][2 * q + 1], afr[mt], &bfr[q][2]);
                }
        }
        __syncthreads();
        if (ch + 2 < NC) issue(p, ch + 2);
        CP_COMMIT();
    }

    // ---------------- epilogue ----------------
    const int gid = lane >> 2;
    const int tig = lane & 3;
    if (MODE == 0) {
        uint32_t* outb = (uint32_t*)g_xw1b;
        float ps[2][2] = {}, pd[2][2] = {};
#pragma unroll
        for (int mt = 0; mt < 2; mt++) {
            int r0 = bm + wm + mt * 16 + gid;
            int r1 = r0 + 8;
#pragma unroll
            for (int nt = 0; nt < 8; nt++) {
                int col = bn + wn + nt * 8 + tig * 2;
                float s0v = asrc[col], s1v = asrc[col + 1];
                float d0v = adst[col], d1v = adst[col + 1];
                float c0 = c[mt][nt][0], c1 = c[mt][nt][1];
                float c2 = c[mt][nt][2], c3 = c[mt][nt][3];
                if (r0 < M) outb[((size_t)r0 * N + col) >> 1] = pack_bf16x2(c0, c1);
                if (r1 < M) outb[((size_t)r1 * N + col) >> 1] = pack_bf16x2(c2, c3);
                ps[mt][0] += c0 * s0v + c1 * s1v;  pd[mt][0] += c0 * d0v + c1 * d1v;
                ps[mt][1] += c2 * s0v + c3 * s1v;  pd[mt][1] += c2 * d0v + c3 * d1v;
            }
        }
#pragma unroll
        for (int o = 1; o <= 2; o <<= 1)
#pragma unroll
            for (int mt = 0; mt < 2; mt++)
#pragma unroll
                for (int h = 0; h < 2; h++) {
                    ps[mt][h] += __shfl_xor_sync(0xffffffffu, ps[mt][h], o);
                    pd[mt][h] += __shfl_xor_sync(0xffffffffu, pd[mt][h], o);
                }
        if (tig == 0) {
#pragma unroll
            for (int mt = 0; mt < 2; mt++)
#pragma unroll
                for (int h = 0; h < 2; h++) {
                    int r = bm + wm + mt * 16 + gid + h * 8;
                    if (r < M) {
                        atomicAdd(&g_a1s[r], ps[mt][h]);
                        atomicAdd(&g_a1d[r], pd[mt][h]);
                    }
                }
        }
    } else {
        float lsum = 0.f;
#pragma unroll
        for (int mt = 0; mt < 2; mt++) {
            int r0 = bm + wm + mt * 16 + gid;
            int r1 = r0 + 8;
#pragma unroll
            for (int nt = 0; nt < 8; nt++) {
                int col = bn + wn + nt * 8 + tig * 2;
                if (r0 < M) {
                    const float* fr = &F[(size_t)r0 * N + col];
                    float d0 = fr[0] - c[mt][nt][0];
                    float d1 = fr[1] - c[mt][nt][1];
                    lsum += d0 * d0 + d1 * d1;
                }
                if (r1 < M) {
                    const float* fr = &F[(size_t)r1 * N + col];
                    float d2 = fr[0] - c[mt][nt][2];
                    float d3 = fr[1] - c[mt][nt][3];
                    lsum += d2 * d2 + d3 * d3;
                }
            }
        }
#pragma unroll
        for (int o = 16; o; o >>= 1) lsum += __shfl_xor_sync(0xffffffffu, lsum, o);
        __shared__ float warp_s[8];
        if (lane == 0) warp_s[wid] = lsum;
        __syncthreads();
        if (tid == 0) {
            float t = 0.f;
#pragma unroll
            for (int w = 0; w < 8; w++) t += warp_s[w];
            atomicAdd(&g_loss, (double)t);
        }
    }
}

// ---------------- single edge pass ------------------------------------------
__global__ void edge_pass(const int* __restrict__ ei) {
    int e = blockIdx.x * blockDim.x + threadIdx.x;
    if (e >= E_TOT) return;
    int s, d;
    if (e < N_EDGES) { s = ei[e]; d = ei[N_EDGES + e]; }
    else             { s = d = e - N_EDGES; }
    float x = g_a1s[s] + g_a1d[d];
    float sig = 1.0f / (1.0f + expf(-x));
    float ex = expf(sig);
    g_ew[e] = ex;
    atomicAdd(&g_den[d], ex);
    atomicAdd(&g_cnt[d], 1);
}

// ---------------- exclusive scan --------------------------------------------
__global__ void scan_kernel() {
    __shared__ int sh[1024];
    int tid = threadIdx.x;
    int carry = 0;
    for (int base = 0; base < N_NODES; base += 1024) {
        int i = base + tid;
        int v = (i < N_NODES) ? g_cnt[i] : 0;
        sh[tid] = v;
        __syncthreads();
        for (int off = 1; off < 1024; off <<= 1) {
            int t = (tid >= off) ? sh[tid - off] : 0;
            __syncthreads();
            sh[tid] += t;
            __syncthreads();
        }
        if (i < N_NODES) g_rowptr[i] = carry + sh[tid] - v;
        int tot = sh[1023];
        __syncthreads();
        carry += tot;
    }
    if (tid == 0) g_rowptr[N_NODES] = carry;
}

// ---------------- CSR fill --------------------------------------------------
__global__ void fill_kernel(const int* __restrict__ ei) {
    int e = blockIdx.x * blockDim.x + threadIdx.x;
    if (e >= E_TOT) return;
    int s, d;
    if (e < N_EDGES) { s = ei[e]; d = ei[N_EDGES + e]; }
    else             { s = d = e - N_EDGES; }
    int pos = atomicAdd(&g_fill[d], 1);
    int idx = g_rowptr[d] + pos;
    g_srcid[idx] = s;
    g_wn[idx] = g_ew[e] / g_den[d];
}

// ---------------- gather-propagate + ELU ------------------------------------
// PASS 0: xw1b -> g_h1 (fp32).  PASS 1: xw3b -> g_h3b (bf16).
template <int PASS>
__global__ __launch_bounds__(256) void gather_kernel() {
    const uint32_t* __restrict__ X =
        (const uint32_t*)((PASS == 0) ? g_xw1b : g_xw3b);
    int gw = (blockIdx.x * blockDim.x + threadIdx.x) >> 5;
    if (gw >= N_NODES) return;
    int lane = threadIdx.x & 31;
    int start = g_rowptr[gw], end = g_rowptr[gw + 1];

    float acc[16];
#pragma unroll
    for (int q = 0; q < 16; q++) acc[q] = 0.f;

    for (int i = start; i < end; i++) {
        int s = g_srcid[i];
        float w = g_wn[i];
        const uint32_t* row = X + (size_t)s * (H1 / 2) + lane * 2;
#pragma unroll
        for (int seg = 0; seg < 4; seg++) {
            uint2 v = *(const uint2*)(row + seg * 64);
            acc[seg * 4 + 0] += w * bf_lo(v.x);
            acc[seg * 4 + 1] += w * bf_hi(v.x);
            acc[seg * 4 + 2] += w * bf_lo(v.y);
            acc[seg * 4 + 3] += w * bf_hi(v.y);
        }
    }
#pragma unroll
    for (int seg = 0; seg < 4; seg++) {
        float a0 = acc[seg * 4 + 0], a1 = acc[seg * 4 + 1];
        float a2 = acc[seg * 4 + 2], a3 = acc[seg * 4 + 3];
        a0 = (a0 > 0.f) ? a0 : expm1f(a0);
        a1 = (a1 > 0.f) ? a1 : expm1f(a1);
        a2 = (a2 > 0.f) ? a2 : expm1f(a2);
        a3 = (a3 > 0.f) ? a3 : expm1f(a3);
        if (PASS == 0) {
            float* yr = g_h1 + (size_t)gw * H1 + lane * 4 + seg * 128;
            *(float4*)yr = make_float4(a0, a1, a2, a3);
        } else {
            uint2* yr = (uint2*)(g_h3b + (size_t)gw * H1 + lane * 4 + seg * 128);
            *yr = make_uint2(pack_bf16x2(a0, a1), pack_bf16x2(a2, a3));
        }
    }
}

// ---------------- fused: h2 = norm(h1@W2); xw3b = bf16(h2@W2^T) -------------
__global__ void h2xw3_kernel(const float* __restrict__ W2) {
    int gw   = (blockIdx.x * blockDim.x + threadIdx.x) >> 5;
    int lane = threadIdx.x & 31;
    int w    = threadIdx.x >> 5;
    __shared__ float sh2[8][32];
    if (gw >= N_NODES) return;
    const float* h1r = g_h1 + (size_t)gw * H1;
    float hj0 = 0.f, hj1 = 0.f;
    if (lane < H2) {
#pragma unroll 4
        for (int k = 0; k < H1; k += 2) {
            hj0 += h1r[k]     * W2[k * H2 + lane];
            hj1 += h1r[k + 1] * W2[(k + 1) * H2 + lane];
        }
    }
    float hj = hj0 + hj1;
    float sq = (lane < H2) ? hj * hj : 0.f;
#pragma unroll
    for (int o = 16; o; o >>= 1) sq += __shfl_xor_sync(0xffffffffu, sq, o);
    float inv = 1.0f / fmaxf(sqrtf(sq), 1e-12f);
    hj *= inv;
    if (lane < H2) sh2[w][lane] = hj;
    __syncwarp();
    __nv_bfloat16* outp = g_xw3b + (size_t)gw * H1;
    for (int k = lane; k < H1; k += 32) {
        float a = 0.f;
#pragma unroll
        for (int j = 0; j < H2; j++)
            a += sh2[w][j] * W2[k * H2 + j];
        outp[k] = __float2bfloat16(a);
    }
}

// ---------------- finalize --------------------------------------------------
__global__ void finalize_kernel(float* out) {
    out[0] = (float)(g_loss / ((double)N_NODES * (double)N_FEAT));
}

// ---------------- launch ----------------------------------------------------
extern "C" void kernel_launch(void* const* d_in, const int* in_sizes, int n_in,
                              void* d_out, int out_size) {
    const float* features = (const float*)d_in[0];
    const int*   edge_idx = (const int*)d_in[1];
    const float* W1       = (const float*)d_in[2];
    const float* att_src1 = (const float*)d_in[3];
    const float* att_dst1 = (const float*)d_in[4];
    const float* W2       = (const float*)d_in[5];
    float* out = (float*)d_out;

    static __nv_bfloat16 *featb_p = nullptr, *w1tb_p = nullptr, *w1b_p = nullptr, *h3b_p = nullptr;
    if (!featb_p) cudaGetSymbolAddress((void**)&featb_p, g_featb);
    if (!w1tb_p)  cudaGetSymbolAddress((void**)&w1tb_p,  g_w1tb);
    if (!w1b_p)   cudaGetSymbolAddress((void**)&w1b_p,   g_w1b);
    if (!h3b_p)   cudaGetSymbolAddress((void**)&h3b_p,   g_h3b);

    init_kernel<<<(N_NODES + 255) / 256, 256>>>();

    convert_feat_kernel<<<2048, 256>>>(features);
    transpose_w1_kernel<<<dim3(H1 / 32, N_FEAT / 32), dim3(32, 8)>>>(W1);
    convert_w1_kernel<<<(N_FEAT * H1 / 4 + 255) / 256, 256>>>(W1);

    // GEMM1: xw1b = bf16(features @ W1) + fused attention logits
    gemm_bf16_kernel<0><<<dim3(H1 / 128, (N_NODES + 127) / 128), 256>>>(
        featb_p, w1tb_p, nullptr, att_src1, att_dst1, N_NODES, H1, N_FEAT);

    int egrid = (E_TOT + 255) / 256;
    edge_pass<<<egrid, 256>>>(edge_idx);
    scan_kernel<<<1, 1024>>>();
    fill_kernel<<<egrid, 256>>>(edge_idx);

    gather_kernel<0><<<(N_NODES * 32 + 255) / 256, 256>>>();

    h2xw3_kernel<<<(N_NODES * 32 + 255) / 256, 256>>>(W2);

    gather_kernel<1><<<(N_NODES * 32 + 255) / 256, 256>>>();

    // GEMM4 + fused MSE: loss = sum((features - h3 @ W1^T)^2)
    gemm_bf16_kernel<1><<<dim3(N_FEAT / 128, (N_NODES + 127) / 128), 256>>>(
        h3b_p, w1b_p, features, nullptr, nullptr, N_NODES, N_FEAT, H1);

    finalize_kernel<<<1, 1>>>(out);
}

// round 6
// speedup vs baseline: 6.0972x; 1.0586x over previous
#include <cuda_runtime.h>
#include <cuda_bf16.h>
#include <math.h>
#include <stdint.h>

#define N_NODES 20000
#define N_EDGES 200000
#define E_TOT   (N_EDGES + N_NODES)
#define N_FEAT  2048
#define H1      512
#define H2      30

// ---------------- device scratch (static, allocation-free) ----------------
__device__ __nv_bfloat16 g_featb[(size_t)N_NODES * N_FEAT]; // bf16 features
__device__ __nv_bfloat16 g_w1tb[(size_t)H1 * N_FEAT];       // bf16 W1^T [512,2048]
__device__ __nv_bfloat16 g_w1b [(size_t)N_FEAT * H1];       // bf16 W1   [2048,512]
__device__ __nv_bfloat16 g_xw1b[(size_t)N_NODES * H1];
__device__ __nv_bfloat16 g_xw3b[(size_t)N_NODES * H1];
__device__ __nv_bfloat16 g_h3b [(size_t)N_NODES * H1];
__device__ float g_a1s[N_NODES];
__device__ float g_a1d[N_NODES];
__device__ float g_den[N_NODES];
__device__ float g_ew [E_TOT];
__device__ int   g_cnt [N_NODES];
__device__ int   g_fill[N_NODES];
__device__ int   g_rowptr[N_NODES + 1];
__device__ int   g_srcid[E_TOT];
__device__ float g_wn  [E_TOT];
__device__ double g_loss;

// ---------------- helpers ---------------------------------------------------
__device__ __forceinline__ uint32_t pack_bf16x2(float lo, float hi) {
    uint32_t r;
    asm("cvt.rn.bf16x2.f32 %0, %1, %2;" : "=r"(r) : "f"(hi), "f"(lo));
    return r;
}
__device__ __forceinline__ float bf_lo(uint32_t u) { return __uint_as_float(u << 16); }
__device__ __forceinline__ float bf_hi(uint32_t u) { return __uint_as_float(u & 0xffff0000u); }

__device__ __forceinline__ void mma_bf16(float* c, const uint32_t* a, const uint32_t* b) {
    asm volatile(
        "mma.sync.aligned.m16n8k16.row.col.f32.bf16.bf16.f32 "
        "{%0,%1,%2,%3}, {%4,%5,%6,%7}, {%8,%9}, {%0,%1,%2,%3};"
        : "+f"(c[0]), "+f"(c[1]), "+f"(c[2]), "+f"(c[3])
        : "r"(a[0]), "r"(a[1]), "r"(a[2]), "r"(a[3]), "r"(b[0]), "r"(b[1]));
}
__device__ __forceinline__ void ldsm4(uint32_t* r, uint32_t a) {
    asm volatile("ldmatrix.sync.aligned.m8n8.x4.shared.b16 {%0,%1,%2,%3}, [%4];"
        : "=r"(r[0]), "=r"(r[1]), "=r"(r[2]), "=r"(r[3]) : "r"(a));
}
__device__ __forceinline__ void cp16(uint32_t dst, const void* src, int sz) {
    asm volatile("cp.async.cg.shared.global [%0], [%1], 16, %2;"
        :: "r"(dst), "l"(src), "r"(sz));
}
#define CP_COMMIT() asm volatile("cp.async.commit_group;" ::: "memory")
#define CP_WAIT1()  asm volatile("cp.async.wait_group 1;" ::: "memory")

__device__ __forceinline__ uint32_t smem_addr_of(const void* p) {
    uint32_t a;
    asm("{ .reg .u64 t; cvta.to.shared.u64 t, %1; cvt.u32.u64 %0, t; }" : "=r"(a) : "l"(p));
    return a;
}

// ---------------- init ------------------------------------------------------
__global__ void init_kernel() {
    int i = blockIdx.x * blockDim.x + threadIdx.x;
    if (i < N_NODES) {
        g_den[i] = 0.0f;
        g_cnt[i] = 0;
        g_fill[i] = 0;
        g_a1s[i] = 0.0f;
        g_a1d[i] = 0.0f;
    }
    if (i == 0) g_loss = 0.0;
}

// ---------------- converts --------------------------------------------------
__global__ void convert_feat_kernel(const float* __restrict__ F) {
    size_t i = (size_t)blockIdx.x * blockDim.x + threadIdx.x;
    size_t n4 = (size_t)N_NODES * N_FEAT / 4;
    uint2* out = (uint2*)g_featb;
    for (; i < n4; i += (size_t)gridDim.x * blockDim.x) {
        float4 v = ((const float4*)F)[i];
        out[i] = make_uint2(pack_bf16x2(v.x, v.y), pack_bf16x2(v.z, v.w));
    }
}
__global__ void convert_w1_kernel(const float* __restrict__ W1) {
    size_t i = (size_t)blockIdx.x * blockDim.x + threadIdx.x;
    size_t n4 = (size_t)N_FEAT * H1 / 4;
    uint2* out = (uint2*)g_w1b;
    if (i < n4) {
        float4 v = ((const float4*)W1)[i];
        out[i] = make_uint2(pack_bf16x2(v.x, v.y), pack_bf16x2(v.z, v.w));
    }
}
__global__ void transpose_w1_kernel(const float* __restrict__ W1) {
    __shared__ float tile[32][33];
    int x = blockIdx.x * 32 + threadIdx.x;
    int y = blockIdx.y * 32 + threadIdx.y;
#pragma unroll
    for (int j = 0; j < 32; j += 8)
        tile[threadIdx.y + j][threadIdx.x] = W1[(size_t)(y + j) * H1 + x];
    __syncthreads();
    int xo = blockIdx.y * 32 + threadIdx.x;
    int yo = blockIdx.x * 32 + threadIdx.y;
#pragma unroll
    for (int j = 0; j < 32; j += 8)
        g_w1tb[(size_t)(yo + j) * N_FEAT + xo] = __float2bfloat16(tile[threadIdx.x][threadIdx.y + j]);
}

#define ROWB  80

// ---------------- GEMM1: 64x128 tile, 3 CTAs/SM -----------------------------
// xw1b = bf16(featb @ w1tb^T) + fused attention logits.
#define G1_AT 5120            // A tile bytes per stage (64 x 80)
#define G1_BT 10240           // B tile bytes per stage (128 x 80)
#define G1_ST (G1_AT + G1_BT)

__global__ __launch_bounds__(256, 3) void gemm1_kernel(
    const float* __restrict__ asrc, const float* __restrict__ adst)
{
    __shared__ __align__(128) char smem[2][G1_ST];

    const __nv_bfloat16* __restrict__ A = g_featb;
    const __nv_bfloat16* __restrict__ B = g_w1tb;
    const int M = N_NODES, N = H1, K = N_FEAT;

    const int tid  = threadIdx.x;
    const int lane = tid & 31;
    const int wid  = tid >> 5;
    const int wm   = (wid & 1) * 32;   // 2 warps over 64 rows
    const int wn   = (wid >> 1) * 32;  // 4 warps over 128 cols
    const int bm   = blockIdx.y * 64;
    const int bn   = blockIdx.x * 128;

    uint32_t sbase = smem_addr_of(smem);

    float c[2][4][4];
#pragma unroll
    for (int mt = 0; mt < 2; mt++)
#pragma unroll
        for (int nt = 0; nt < 4; nt++)
#pragma unroll
            for (int q = 0; q < 4; q++) c[mt][nt][q] = 0.f;

    const int NC = K / 32;
    const int rA = tid >> 2, sg = tid & 3;   // A: 1 op (row 0..63)
    const int rB0 = tid >> 2, rB1 = rB0 + 64;

    uint32_t aoff[2], boff[2];
#pragma unroll
    for (int mt = 0; mt < 2; mt++)
        aoff[mt] = (uint32_t)((wm + mt * 16 + (lane & 15)) * ROWB + (lane >> 4) * 16);
#pragma unroll
    for (int q = 0; q < 2; q++)
        boff[q] = (uint32_t)(G1_AT + (wn + q * 16 + (lane & 7) + ((lane >> 4) << 3)) * ROWB
                             + ((lane >> 3) & 1) * 16);

    auto issue = [&](int p, int ch) {
        uint32_t ab = sbase + p * G1_ST;
        uint32_t bb = ab + G1_AT;
        int k0 = ch * 32;
        int am = bm + rA;
        cp16(ab + rA * ROWB + sg * 16, A + (size_t)am * K + k0 + sg * 8, am < M ? 16 : 0);
        cp16(bb + rB0 * ROWB + sg * 16, B + (size_t)(bn + rB0) * K + k0 + sg * 8, 16);
        cp16(bb + rB1 * ROWB + sg * 16, B + (size_t)(bn + rB1) * K + k0 + sg * 8, 16);
    };

    issue(0, 0); CP_COMMIT();
    issue(1, 1); CP_COMMIT();

    for (int ch = 0; ch < NC; ch++) {
        int p = ch & 1;
        CP_WAIT1();
        __syncthreads();
        uint32_t tb = sbase + p * G1_ST;
#pragma unroll
        for (int ks = 0; ks < 2; ks++) {
            uint32_t afr[2][4];
#pragma unroll
            for (int mt = 0; mt < 2; mt++) ldsm4(afr[mt], tb + aoff[mt] + ks * 32);
            uint32_t bfr[2][4];
#pragma unroll
            for (int q = 0; q < 2; q++) ldsm4(bfr[q], tb + boff[q] + ks * 32);
#pragma unroll
            for (int mt = 0; mt < 2; mt++)
#pragma unroll
                for (int q = 0; q < 2; q++) {
                    mma_bf16(c[mt][2 * q],     afr[mt], &bfr[q][0]);
                    mma_bf16(c[mt][2 * q + 1], afr[mt], &bfr[q][2]);
                }
        }
        __syncthreads();
        if (ch + 2 < NC) issue(p, ch + 2);
        CP_COMMIT();
    }

    // epilogue: bf16 store + attention logit partials
    const int gid = lane >> 2;
    const int tig = lane & 3;
    uint32_t* outb = (uint32_t*)g_xw1b;
    float ps[2][2] = {}, pd[2][2] = {};
#pragma unroll
    for (int mt = 0; mt < 2; mt++) {
        int r0 = bm + wm + mt * 16 + gid;
        int r1 = r0 + 8;
#pragma unroll
        for (int nt = 0; nt < 4; nt++) {
            int col = bn + wn + nt * 8 + tig * 2;
            float s0v = asrc[col], s1v = asrc[col + 1];
            float d0v = adst[col], d1v = adst[col + 1];
            float c0 = c[mt][nt][0], c1 = c[mt][nt][1];
            float c2 = c[mt][nt][2], c3 = c[mt][nt][3];
            if (r0 < M) outb[((size_t)r0 * N + col) >> 1] = pack_bf16x2(c0, c1);
            if (r1 < M) outb[((size_t)r1 * N + col) >> 1] = pack_bf16x2(c2, c3);
            ps[0][0] = ps[mt][0] + ((mt == 0) ? 0.f : 0.f); // (keep structure simple below)
            ps[mt][0] += c0 * s0v + c1 * s1v;  pd[mt][0] += c0 * d0v + c1 * d1v;
            ps[mt][1] += c2 * s0v + c3 * s1v;  pd[mt][1] += c2 * d0v + c3 * d1v;
        }
    }
#pragma unroll
    for (int o = 1; o <= 2; o <<= 1)
#pragma unroll
        for (int mt = 0; mt < 2; mt++)
#pragma unroll
            for (int h = 0; h < 2; h++) {
                ps[mt][h] += __shfl_xor_sync(0xffffffffu, ps[mt][h], o);
                pd[mt][h] += __shfl_xor_sync(0xffffffffu, pd[mt][h], o);
            }
    if (tig == 0) {
#pragma unroll
        for (int mt = 0; mt < 2; mt++)
#pragma unroll
            for (int h = 0; h < 2; h++) {
                int r = bm + wm + mt * 16 + gid + h * 8;
                if (r < M) {
                    atomicAdd(&g_a1s[r], ps[mt][h]);
                    atomicAdd(&g_a1d[r], pd[mt][h]);
                }
            }
    }
}

// ---------------- GEMM4: 128x128 tile, fused MSE (bf16 F) -------------------
#define G4_T  10240
#define G4_ST (2 * G4_T)

__global__ __launch_bounds__(256, 2) void gemm4_kernel() {
    __shared__ __align__(128) char smem[2][G4_ST];

    const __nv_bfloat16* __restrict__ A = g_h3b;
    const __nv_bfloat16* __restrict__ B = g_w1b;
    const int M = N_NODES, N = N_FEAT, K = H1;

    const int tid  = threadIdx.x;
    const int lane = tid & 31;
    const int wid  = tid >> 5;
    const int wm   = (wid & 3) * 32;
    const int wn   = (wid >> 2) * 64;
    const int bm   = blockIdx.y * 128;
    const int bn   = blockIdx.x * 128;

    uint32_t sbase = smem_addr_of(smem);

    float c[2][8][4];
#pragma unroll
    for (int mt = 0; mt < 2; mt++)
#pragma unroll
        for (int nt = 0; nt < 8; nt++)
#pragma unroll
            for (int q = 0; q < 4; q++) c[mt][nt][q] = 0.f;

    const int NC = K / 32;
    const int r0c = tid >> 2, sg = tid & 3;
    const int r1c = r0c + 64;

    uint32_t aoff[2], boff[4];
#pragma unroll
    for (int mt = 0; mt < 2; mt++)
        aoff[mt] = (uint32_t)((wm + mt * 16 + (lane & 15)) * ROWB + (lane >> 4) * 16);
#pragma unroll
    for (int q = 0; q < 4; q++)
        boff[q] = (uint32_t)(G4_T + (wn + q * 16 + (lane & 7) + ((lane >> 4) << 3)) * ROWB
                             + ((lane >> 3) & 1) * 16);

    auto issue = [&](int p, int ch) {
        uint32_t ab = sbase + p * G4_ST;
        uint32_t bb = ab + G4_T;
        int k0 = ch * 32;
        int am0 = bm + r0c, am1 = bm + r1c;
        cp16(ab + r0c * ROWB + sg * 16, A + (size_t)am0 * K + k0 + sg * 8, am0 < M ? 16 : 0);
        cp16(ab + r1c * ROWB + sg * 16, A + (size_t)am1 * K + k0 + sg * 8, am1 < M ? 16 : 0);
        cp16(bb + r0c * ROWB + sg * 16, B + (size_t)(bn + r0c) * K + k0 + sg * 8, 16);
        cp16(bb + r1c * ROWB + sg * 16, B + (size_t)(bn + r1c) * K + k0 + sg * 8, 16);
    };

    issue(0, 0); CP_COMMIT();
    issue(1, 1); CP_COMMIT();

    for (int ch = 0; ch < NC; ch++) {
        int p = ch & 1;
        CP_WAIT1();
        __syncthreads();
        uint32_t tb = sbase + p * G4_ST;
#pragma unroll
        for (int ks = 0; ks < 2; ks++) {
            uint32_t afr[2][4];
#pragma unroll
            for (int mt = 0; mt < 2; mt++) ldsm4(afr[mt], tb + aoff[mt] + ks * 32);
            uint32_t bfr[4][4];
#pragma unroll
            for (int q = 0; q < 4; q++) ldsm4(bfr[q], tb + boff[q] + ks * 32);
#pragma unroll
            for (int mt = 0; mt < 2; mt++)
#pragma unroll
                for (int q = 0; q < 4; q++) {
                    mma_bf16(c[mt][2 * q],     afr[mt], &bfr[q][0]);
                    mma_bf16(c[mt][2 * q + 1], afr[mt], &bfr[q][2]);
                }
        }
        __syncthreads();
        if (ch + 2 < NC) issue(p, ch + 2);
        CP_COMMIT();
    }

    // fused MSE vs bf16 features
    const int gid = lane >> 2;
    const int tig = lane & 3;
    const uint32_t* fb = (const uint32_t*)g_featb;
    float lsum = 0.f;
#pragma unroll
    for (int mt = 0; mt < 2; mt++) {
        int r0 = bm + wm + mt * 16 + gid;
        int r1 = r0 + 8;
#pragma unroll
        for (int nt = 0; nt < 8; nt++) {
            int col = bn + wn + nt * 8 + tig * 2;
            if (r0 < M) {
                uint32_t u = fb[((size_t)r0 * N + col) >> 1];
                float d0 = bf_lo(u) - c[mt][nt][0];
                float d1 = bf_hi(u) - c[mt][nt][1];
                lsum += d0 * d0 + d1 * d1;
            }
            if (r1 < M) {
                uint32_t u = fb[((size_t)r1 * N + col) >> 1];
                float d2 = bf_lo(u) - c[mt][nt][2];
                float d3 = bf_hi(u) - c[mt][nt][3];
                lsum += d2 * d2 + d3 * d3;
            }
        }
    }
#pragma unroll
    for (int o = 16; o; o >>= 1) lsum += __shfl_xor_sync(0xffffffffu, lsum, o);
    __shared__ float warp_s[8];
    if (lane == 0) warp_s[wid] = lsum;
    __syncthreads();
    if (tid == 0) {
        float t = 0.f;
#pragma unroll
        for (int w = 0; w < 8; w++) t += warp_s[w];
        atomicAdd(&g_loss, (double)t);
    }
}

// ---------------- single edge pass ------------------------------------------
__global__ void edge_pass(const int* __restrict__ ei) {
    int e = blockIdx.x * blockDim.x + threadIdx.x;
    if (e >= E_TOT) return;
    int s, d;
    if (e < N_EDGES) { s = ei[e]; d = ei[N_EDGES + e]; }
    else             { s = d = e - N_EDGES; }
    float x = g_a1s[s] + g_a1d[d];
    float sig = 1.0f / (1.0f + expf(-x));
    float ex = expf(sig);
    g_ew[e] = ex;
    atomicAdd(&g_den[d], ex);
    atomicAdd(&g_cnt[d], 1);
}

// ---------------- exclusive scan (shfl-based) -------------------------------
__global__ void scan_kernel() {
    __shared__ int wsum[32];
    int tid = threadIdx.x, lane = tid & 31, w = tid >> 5;
    int carry = 0;
    for (int base = 0; base < N_NODES; base += 1024) {
        int i = base + tid;
        int v = (i < N_NODES) ? g_cnt[i] : 0;
        int inc = v;
#pragma unroll
        for (int o = 1; o <= 16; o <<= 1) {
            int t = __shfl_up_sync(0xffffffffu, inc, o);
            if (lane >= o) inc += t;
        }
        if (lane == 31) wsum[w] = inc;
        __syncthreads();
        if (w == 0) {
            int s = wsum[lane];
#pragma unroll
            for (int o = 1; o <= 16; o <<= 1) {
                int t = __shfl_up_sync(0xffffffffu, s, o);
                if (lane >= o) s += t;
            }
            wsum[lane] = s;
        }
        __syncthreads();
        int off = (w > 0) ? wsum[w - 1] : 0;
        if (i < N_NODES) g_rowptr[i] = carry + off + inc - v;
        int tot = wsum[31];
        __syncthreads();
        carry += tot;
    }
    if (tid == 0) g_rowptr[N_NODES] = carry;
}

// ---------------- CSR fill --------------------------------------------------
__global__ void fill_kernel(const int* __restrict__ ei) {
    int e = blockIdx.x * blockDim.x + threadIdx.x;
    if (e >= E_TOT) return;
    int s, d;
    if (e < N_EDGES) { s = ei[e]; d = ei[N_EDGES + e]; }
    else             { s = d = e - N_EDGES; }
    int pos = atomicAdd(&g_fill[d], 1);
    int idx = g_rowptr[d] + pos;
    g_srcid[idx] = s;
    g_wn[idx] = g_ew[e] / g_den[d];
}

// ---------------- fused gather<0> + ELU + h2-normalize + xw3 ----------------
// warp per node: gather h1 row (512 cols) into regs, stage to smem,
// h2 = normalize(h1 @ W2), xw3b = bf16(h2 @ W2^T).
__global__ __launch_bounds__(256) void gather0_h2_kernel(const float* __restrict__ W2) {
    __shared__ float h1row[8][512];
    __shared__ float sh2[8][32];
    int gw = (blockIdx.x * blockDim.x + threadIdx.x) >> 5;
    if (gw >= N_NODES) return;
    int lane = threadIdx.x & 31;
    int w = threadIdx.x >> 5;
    int start = g_rowptr[gw], end = g_rowptr[gw + 1];

    const uint32_t* __restrict__ X = (const uint32_t*)g_xw1b;
    float acc[16];
#pragma unroll
    for (int q = 0; q < 16; q++) acc[q] = 0.f;

    for (int i = start; i < end; i++) {
        int s = g_srcid[i];
        float wgt = g_wn[i];
        const uint32_t* row = X + (size_t)s * (H1 / 2) + lane * 2;
#pragma unroll
        for (int seg = 0; seg < 4; seg++) {
            uint2 v = *(const uint2*)(row + seg * 64);
            acc[seg * 4 + 0] += wgt * bf_lo(v.x);
            acc[seg * 4 + 1] += wgt * bf_hi(v.x);
            acc[seg * 4 + 2] += wgt * bf_lo(v.y);
            acc[seg * 4 + 3] += wgt * bf_hi(v.y);
        }
    }
    // ELU + stage full h1 row to smem
#pragma unroll
    for (int seg = 0; seg < 4; seg++) {
        float a0 = acc[seg * 4 + 0], a1 = acc[seg * 4 + 1];
        float a2 = acc[seg * 4 + 2], a3 = acc[seg * 4 + 3];
        a0 = (a0 > 0.f) ? a0 : expm1f(a0);
        a1 = (a1 > 0.f) ? a1 : expm1f(a1);
        a2 = (a2 > 0.f) ? a2 : expm1f(a2);
        a3 = (a3 > 0.f) ? a3 : expm1f(a3);
        *(float4*)&h1row[w][seg * 128 + lane * 4] = make_float4(a0, a1, a2, a3);
    }
    __syncwarp();

    // h2 = h1 @ W2 (lane j < 30 handles output j)
    float hj0 = 0.f, hj1 = 0.f;
    if (lane < H2) {
#pragma unroll 4
        for (int k = 0; k < H1; k += 2) {
            hj0 += h1row[w][k]     * W2[k * H2 + lane];
            hj1 += h1row[w][k + 1] * W2[(k + 1) * H2 + lane];
        }
    }
    float hj = hj0 + hj1;
    float sq = (lane < H2) ? hj * hj : 0.f;
#pragma unroll
    for (int o = 16; o; o >>= 1) sq += __shfl_xor_sync(0xffffffffu, sq, o);
    float inv = 1.0f / fmaxf(sqrtf(sq), 1e-12f);
    hj *= inv;
    if (lane < H2) sh2[w][lane] = hj;
    __syncwarp();

    // xw3 = h2 @ W2^T  -> bf16
    __nv_bfloat16* outp = g_xw3b + (size_t)gw * H1;
    for (int k = lane; k < H1; k += 32) {
        float a = 0.f;
#pragma unroll
        for (int j = 0; j < H2; j++)
            a += sh2[w][j] * W2[k * H2 + j];
        outp[k] = __float2bfloat16(a);
    }
}

// ---------------- gather<1>: xw3b -> h3b (bf16) -----------------------------
__global__ __launch_bounds__(256) void gather1_kernel() {
    const uint32_t* __restrict__ X = (const uint32_t*)g_xw3b;
    int gw = (blockIdx.x * blockDim.x + threadIdx.x) >> 5;
    if (gw >= N_NODES) return;
    int lane = threadIdx.x & 31;
    int start = g_rowptr[gw], end = g_rowptr[gw + 1];

    float acc[16];
#pragma unroll
    for (int q = 0; q < 16; q++) acc[q] = 0.f;

    for (int i = start; i < end; i++) {
        int s = g_srcid[i];
        float wgt = g_wn[i];
        const uint32_t* row = X + (size_t)s * (H1 / 2) + lane * 2;
#pragma unroll
        for (int seg = 0; seg < 4; seg++) {
            uint2 v = *(const uint2*)(row + seg * 64);
            acc[seg * 4 + 0] += wgt * bf_lo(v.x);
            acc[seg * 4 + 1] += wgt * bf_hi(v.x);
            acc[seg * 4 + 2] += wgt * bf_lo(v.y);
            acc[seg * 4 + 3] += wgt * bf_hi(v.y);
        }
    }
#pragma unroll
    for (int seg = 0; seg < 4; seg++) {
        float a0 = acc[seg * 4 + 0], a1 = acc[seg * 4 + 1];
        float a2 = acc[seg * 4 + 2], a3 = acc[seg * 4 + 3];
        a0 = (a0 > 0.f) ? a0 : expm1f(a0);
        a1 = (a1 > 0.f) ? a1 : expm1f(a1);
        a2 = (a2 > 0.f) ? a2 : expm1f(a2);
        a3 = (a3 > 0.f) ? a3 : expm1f(a3);
        uint2* yr = (uint2*)(g_h3b + (size_t)gw * H1 + lane * 4 + seg * 128);
        *yr = make_uint2(pack_bf16x2(a0, a1), pack_bf16x2(a2, a3));
    }
}

// ---------------- finalize --------------------------------------------------
__global__ void finalize_kernel(float* out) {
    out[0] = (float)(g_loss / ((double)N_NODES * (double)N_FEAT));
}

// ---------------- launch ----------------------------------------------------
extern "C" void kernel_launch(void* const* d_in, const int* in_sizes, int n_in,
                              void* d_out, int out_size) {
    const float* features = (const float*)d_in[0];
    const int*   edge_idx = (const int*)d_in[1];
    const float* W1       = (const float*)d_in[2];
    const float* att_src1 = (const float*)d_in[3];
    const float* att_dst1 = (const float*)d_in[4];
    const float* W2       = (const float*)d_in[5];
    float* out = (float*)d_out;

    init_kernel<<<(N_NODES + 255) / 256, 256>>>();

    convert_feat_kernel<<<2048, 256>>>(features);
    transpose_w1_kernel<<<dim3(H1 / 32, N_FEAT / 32), dim3(32, 8)>>>(W1);
    convert_w1_kernel<<<(N_FEAT * H1 / 4 + 255) / 256, 256>>>(W1);

    // GEMM1: 64x128 tiles, grid (4, 313)
    gemm1_kernel<<<dim3(H1 / 128, (N_NODES + 63) / 64), 256>>>(att_src1, att_dst1);

    int egrid = (E_TOT + 255) / 256;
    edge_pass<<<egrid, 256>>>(edge_idx);
    scan_kernel<<<1, 1024>>>();
    fill_kernel<<<egrid, 256>>>(edge_idx);

    gather0_h2_kernel<<<(N_NODES * 32 + 255) / 256, 256>>>(W2);

    gather1_kernel<<<(N_NODES * 32 + 255) / 256, 256>>>();

    // GEMM4 + fused MSE
    gemm4_kernel<<<dim3(N_FEAT / 128, (N_NODES + 127) / 128), 256>>>();

    finalize_kernel<<<1, 1>>>(out);
}

// round 7
// speedup vs baseline: 6.1856x; 1.0145x over previous
#include <cuda_runtime.h>
#include <cuda_bf16.h>
#include <math.h>
#include <stdint.h>

#define N_NODES 20000
#define N_EDGES 200000
#define E_TOT   (N_EDGES + N_NODES)
#define N_FEAT  2048
#define H1      512
#define H2      30

// ---------------- device scratch (static, allocation-free) ----------------
__device__ __nv_bfloat16 g_featb[(size_t)N_NODES * N_FEAT]; // bf16 features
__device__ __nv_bfloat16 g_w1tb[(size_t)H1 * N_FEAT];       // bf16 W1^T [512,2048]
__device__ __nv_bfloat16 g_w1b [(size_t)N_FEAT * H1];       // bf16 W1   [2048,512]
__device__ __nv_bfloat16 g_xw1b[(size_t)N_NODES * H1];
__device__ __nv_bfloat16 g_xw3b[(size_t)N_NODES * H1];
__device__ __nv_bfloat16 g_h3b [(size_t)N_NODES * H1];
__device__ float g_a1s[N_NODES];
__device__ float g_a1d[N_NODES];
__device__ float g_den[N_NODES];
__device__ float g_ew [E_TOT];
__device__ int   g_cnt [N_NODES];
__device__ int   g_fill[N_NODES];
__device__ int   g_rowptr[N_NODES + 1];
__device__ int   g_srcid[E_TOT];
__device__ float g_wn  [E_TOT];
__device__ double g_loss;

// ---------------- helpers ---------------------------------------------------
__device__ __forceinline__ uint32_t pack_bf16x2(float lo, float hi) {
    uint32_t r;
    asm("cvt.rn.bf16x2.f32 %0, %1, %2;" : "=r"(r) : "f"(hi), "f"(lo));
    return r;
}
__device__ __forceinline__ float bf_lo(uint32_t u) { return __uint_as_float(u << 16); }
__device__ __forceinline__ float bf_hi(uint32_t u) { return __uint_as_float(u & 0xffff0000u); }

__device__ __forceinline__ void mma_bf16(float* c, const uint32_t* a, const uint32_t* b) {
    asm volatile(
        "mma.sync.aligned.m16n8k16.row.col.f32.bf16.bf16.f32 "
        "{%0,%1,%2,%3}, {%4,%5,%6,%7}, {%8,%9}, {%0,%1,%2,%3};"
        : "+f"(c[0]), "+f"(c[1]), "+f"(c[2]), "+f"(c[3])
        : "r"(a[0]), "r"(a[1]), "r"(a[2]), "r"(a[3]), "r"(b[0]), "r"(b[1]));
}
__device__ __forceinline__ void ldsm4(uint32_t* r, uint32_t a) {
    asm volatile("ldmatrix.sync.aligned.m8n8.x4.shared.b16 {%0,%1,%2,%3}, [%4];"
        : "=r"(r[0]), "=r"(r[1]), "=r"(r[2]), "=r"(r[3]) : "r"(a));
}
__device__ __forceinline__ void cp16(uint32_t dst, const void* src, int sz) {
    asm volatile("cp.async.cg.shared.global [%0], [%1], 16, %2;"
        :: "r"(dst), "l"(src), "r"(sz));
}
#define CP_COMMIT() asm volatile("cp.async.commit_group;" ::: "memory")
#define CP_WAIT1()  asm volatile("cp.async.wait_group 1;" ::: "memory")

__device__ __forceinline__ uint32_t smem_addr_of(const void* p) {
    uint32_t a;
    asm("{ .reg .u64 t; cvta.to.shared.u64 t, %1; cvt.u32.u64 %0, t; }" : "=r"(a) : "l"(p));
    return a;
}

// ---------------- init ------------------------------------------------------
__global__ void init_kernel() {
    int i = blockIdx.x * blockDim.x + threadIdx.x;
    if (i < N_NODES) {
        g_den[i] = 0.0f;
        g_cnt[i] = 0;
        g_fill[i] = 0;
        g_a1s[i] = 0.0f;
        g_a1d[i] = 0.0f;
    }
    if (i == 0) g_loss = 0.0;
}

// ---------------- converts --------------------------------------------------
__global__ void convert_feat_kernel(const float* __restrict__ F) {
    size_t i = (size_t)blockIdx.x * blockDim.x + threadIdx.x;
    size_t n4 = (size_t)N_NODES * N_FEAT / 4;
    uint2* out = (uint2*)g_featb;
    for (; i < n4; i += (size_t)gridDim.x * blockDim.x) {
        float4 v = ((const float4*)F)[i];
        out[i] = make_uint2(pack_bf16x2(v.x, v.y), pack_bf16x2(v.z, v.w));
    }
}
// transpose W1 -> g_w1tb (bf16) AND straight-convert -> g_w1b (bf16)
__global__ void prep_w1_kernel(const float* __restrict__ W1) {
    __shared__ float tile[32][33];
    int x = blockIdx.x * 32 + threadIdx.x;  // col (0..511)
    int y = blockIdx.y * 32 + threadIdx.y;  // row (0..2047)
#pragma unroll
    for (int j = 0; j < 32; j += 8) {
        float v = W1[(size_t)(y + j) * H1 + x];
        tile[threadIdx.y + j][threadIdx.x] = v;
        g_w1b[(size_t)(y + j) * H1 + x] = __float2bfloat16(v);
    }
    __syncthreads();
    int xo = blockIdx.y * 32 + threadIdx.x;
    int yo = blockIdx.x * 32 + threadIdx.y;
#pragma unroll
    for (int j = 0; j < 32; j += 8)
        g_w1tb[(size_t)(yo + j) * N_FEAT + xo] = __float2bfloat16(tile[threadIdx.x][threadIdx.y + j]);
}

#define ROWB  80

// ---------------- GEMM1: 64x128 tile, 3-stage single-sync pipeline ----------
#define G1_AT 5120
#define G1_BT 10240
#define G1_ST (G1_AT + G1_BT)

__global__ __launch_bounds__(256, 3) void gemm1_kernel(
    const float* __restrict__ asrc, const float* __restrict__ adst)
{
    __shared__ __align__(128) char smem[3][G1_ST];

    const __nv_bfloat16* __restrict__ A = g_featb;
    const __nv_bfloat16* __restrict__ B = g_w1tb;
    const int M = N_NODES, N = H1, K = N_FEAT;

    const int tid  = threadIdx.x;
    const int lane = tid & 31;
    const int wid  = tid >> 5;
    const int wm   = (wid & 1) * 32;
    const int wn   = (wid >> 1) * 32;
    const int bm   = blockIdx.y * 64;
    const int bn   = blockIdx.x * 128;

    uint32_t sbase = smem_addr_of(smem);

    float c[2][4][4];
#pragma unroll
    for (int mt = 0; mt < 2; mt++)
#pragma unroll
        for (int nt = 0; nt < 4; nt++)
#pragma unroll
            for (int q = 0; q < 4; q++) c[mt][nt][q] = 0.f;

    const int NC = K / 32;
    const int rA = tid >> 2, sg = tid & 3;
    const int rB0 = tid >> 2, rB1 = rB0 + 64;

    uint32_t aoff[2], boff[2];
#pragma unroll
    for (int mt = 0; mt < 2; mt++)
        aoff[mt] = (uint32_t)((wm + mt * 16 + (lane & 15)) * ROWB + (lane >> 4) * 16);
#pragma unroll
    for (int q = 0; q < 2; q++)
        boff[q] = (uint32_t)(G1_AT + (wn + q * 16 + (lane & 7) + ((lane >> 4) << 3)) * ROWB
                             + ((lane >> 3) & 1) * 16);

    auto issue = [&](int p, int ch) {
        uint32_t ab = sbase + p * G1_ST;
        uint32_t bb = ab + G1_AT;
        int k0 = ch * 32;
        int am = bm + rA;
        cp16(ab + rA * ROWB + sg * 16, A + (size_t)am * K + k0 + sg * 8, am < M ? 16 : 0);
        cp16(bb + rB0 * ROWB + sg * 16, B + (size_t)(bn + rB0) * K + k0 + sg * 8, 16);
        cp16(bb + rB1 * ROWB + sg * 16, B + (size_t)(bn + rB1) * K + k0 + sg * 8, 16);
    };

    issue(0, 0); CP_COMMIT();
    issue(1, 1); CP_COMMIT();

    int p = 0;
    for (int ch = 0; ch < NC; ch++) {
        CP_WAIT1();
        __syncthreads();
        uint32_t tb = sbase + p * G1_ST;
#pragma unroll
        for (int ks = 0; ks < 2; ks++) {
            uint32_t afr[2][4];
#pragma unroll
            for (int mt = 0; mt < 2; mt++) ldsm4(afr[mt], tb + aoff[mt] + ks * 32);
            uint32_t bfr[2][4];
#pragma unroll
            for (int q = 0; q < 2; q++) ldsm4(bfr[q], tb + boff[q] + ks * 32);
#pragma unroll
            for (int mt = 0; mt < 2; mt++)
#pragma unroll
                for (int q = 0; q < 2; q++) {
                    mma_bf16(c[mt][2 * q],     afr[mt], &bfr[q][0]);
                    mma_bf16(c[mt][2 * q + 1], afr[mt], &bfr[q][2]);
                }
        }
        // issue chunk ch+2 into buffer (p+2)%3 (computed last iter; safe past the sync)
        if (ch + 2 < NC) {
            int pn = p + 2; if (pn >= 3) pn -= 3;
            issue(pn, ch + 2);
        }
        CP_COMMIT();
        if (++p == 3) p = 0;
    }

    // epilogue: bf16 store + attention logit partials
    const int gid = lane >> 2;
    const int tig = lane & 3;
    uint32_t* outb = (uint32_t*)g_xw1b;
    float ps[2][2] = {}, pd[2][2] = {};
#pragma unroll
    for (int mt = 0; mt < 2; mt++) {
        int r0 = bm + wm + mt * 16 + gid;
        int r1 = r0 + 8;
#pragma unroll
        for (int nt = 0; nt < 4; nt++) {
            int col = bn + wn + nt * 8 + tig * 2;
            float s0v = asrc[col], s1v = asrc[col + 1];
            float d0v = adst[col], d1v = adst[col + 1];
            float c0 = c[mt][nt][0], c1 = c[mt][nt][1];
            float c2 = c[mt][nt][2], c3 = c[mt][nt][3];
            if (r0 < M) outb[((size_t)r0 * N + col) >> 1] = pack_bf16x2(c0, c1);
            if (r1 < M) outb[((size_t)r1 * N + col) >> 1] = pack_bf16x2(c2, c3);
            ps[mt][0] += c0 * s0v + c1 * s1v;  pd[mt][0] += c0 * d0v + c1 * d1v;
            ps[mt][1] += c2 * s0v + c3 * s1v;  pd[mt][1] += c2 * d0v + c3 * d1v;
        }
    }
#pragma unroll
    for (int o = 1; o <= 2; o <<= 1)
#pragma unroll
        for (int mt = 0; mt < 2; mt++)
#pragma unroll
            for (int h = 0; h < 2; h++) {
                ps[mt][h] += __shfl_xor_sync(0xffffffffu, ps[mt][h], o);
                pd[mt][h] += __shfl_xor_sync(0xffffffffu, pd[mt][h], o);
            }
    if (tig == 0) {
#pragma unroll
        for (int mt = 0; mt < 2; mt++)
#pragma unroll
            for (int h = 0; h < 2; h++) {
                int r = bm + wm + mt * 16 + gid + h * 8;
                if (r < M) {
                    atomicAdd(&g_a1s[r], ps[mt][h]);
                    atomicAdd(&g_a1d[r], pd[mt][h]);
                }
            }
    }
}

// ---------------- GEMM4: 128x128 tile, 3-stage, dynamic smem, fused MSE -----
#define G4_T   10240
#define G4_ST  (2 * G4_T)
#define G4_DYN (3 * G4_ST)

__global__ __launch_bounds__(256, 2) void gemm4_kernel() {
    extern __shared__ __align__(128) char smem4[];

    const __nv_bfloat16* __restrict__ A = g_h3b;
    const __nv_bfloat16* __restrict__ B = g_w1b;
    const int M = N_NODES, N = N_FEAT, K = H1;

    const int tid  = threadIdx.x;
    const int lane = tid & 31;
    const int wid  = tid >> 5;
    const int wm   = (wid & 3) * 32;
    const int wn   = (wid >> 2) * 64;
    const int bm   = blockIdx.y * 128;
    const int bn   = blockIdx.x * 128;

    uint32_t sbase = smem_addr_of(smem4);

    float c[2][8][4];
#pragma unroll
    for (int mt = 0; mt < 2; mt++)
#pragma unroll
        for (int nt = 0; nt < 8; nt++)
#pragma unroll
            for (int q = 0; q < 4; q++) c[mt][nt][q] = 0.f;

    const int NC = K / 32;
    const int r0c = tid >> 2, sg = tid & 3;
    const int r1c = r0c + 64;

    uint32_t aoff[2], boff[4];
#pragma unroll
    for (int mt = 0; mt < 2; mt++)
        aoff[mt] = (uint32_t)((wm + mt * 16 + (lane & 15)) * ROWB + (lane >> 4) * 16);
#pragma unroll
    for (int q = 0; q < 4; q++)
        boff[q] = (uint32_t)(G4_T + (wn + q * 16 + (lane & 7) + ((lane >> 4) << 3)) * ROWB
                             + ((lane >> 3) & 1) * 16);

    auto issue = [&](int p, int ch) {
        uint32_t ab = sbase + p * G4_ST;
        uint32_t bb = ab + G4_T;
        int k0 = ch * 32;
        int am0 = bm + r0c, am1 = bm + r1c;
        cp16(ab + r0c * ROWB + sg * 16, A + (size_t)am0 * K + k0 + sg * 8, am0 < M ? 16 : 0);
        cp16(ab + r1c * ROWB + sg * 16, A + (size_t)am1 * K + k0 + sg * 8, am1 < M ? 16 : 0);
        cp16(bb + r0c * ROWB + sg * 16, B + (size_t)(bn + r0c) * K + k0 + sg * 8, 16);
        cp16(bb + r1c * ROWB + sg * 16, B + (size_t)(bn + r1c) * K + k0 + sg * 8, 16);
    };

    issue(0, 0); CP_COMMIT();
    issue(1, 1); CP_COMMIT();

    int p = 0;
    for (int ch = 0; ch < NC; ch++) {
        CP_WAIT1();
        __syncthreads();
        uint32_t tb = sbase + p * G4_ST;
#pragma unroll
        for (int ks = 0; ks < 2; ks++) {
            uint32_t afr[2][4];
#pragma unroll
            for (int mt = 0; mt < 2; mt++) ldsm4(afr[mt], tb + aoff[mt] + ks * 32);
            uint32_t bfr[4][4];
#pragma unroll
            for (int q = 0; q < 4; q++) ldsm4(bfr[q], tb + boff[q] + ks * 32);
#pragma unroll
            for (int mt = 0; mt < 2; mt++)
#pragma unroll
                for (int q = 0; q < 4; q++) {
                    mma_bf16(c[mt][2 * q],     afr[mt], &bfr[q][0]);
                    mma_bf16(c[mt][2 * q + 1], afr[mt], &bfr[q][2]);
                }
        }
        if (ch + 2 < NC) {
            int pn = p + 2; if (pn >= 3) pn -= 3;
            issue(pn, ch + 2);
        }
        CP_COMMIT();
        if (++p == 3) p = 0;
    }

    // fused MSE vs bf16 features
    const int gid = lane >> 2;
    const int tig = lane & 3;
    const uint32_t* fb = (const uint32_t*)g_featb;
    float lsum = 0.f;
#pragma unroll
    for (int mt = 0; mt < 2; mt++) {
        int r0 = bm + wm + mt * 16 + gid;
        int r1 = r0 + 8;
#pragma unroll
        for (int nt = 0; nt < 8; nt++) {
            int col = bn + wn + nt * 8 + tig * 2;
            if (r0 < M) {
                uint32_t u = fb[((size_t)r0 * N + col) >> 1];
                float d0 = bf_lo(u) - c[mt][nt][0];
                float d1 = bf_hi(u) - c[mt][nt][1];
                lsum += d0 * d0 + d1 * d1;
            }
            if (r1 < M) {
                uint32_t u = fb[((size_t)r1 * N + col) >> 1];
                float d2 = bf_lo(u) - c[mt][nt][2];
                float d3 = bf_hi(u) - c[mt][nt][3];
                lsum += d2 * d2 + d3 * d3;
            }
        }
    }
#pragma unroll
    for (int o = 16; o; o >>= 1) lsum += __shfl_xor_sync(0xffffffffu, lsum, o);
    __shared__ float warp_s[8];
    if (lane == 0) warp_s[wid] = lsum;
    __syncthreads();
    if (tid == 0) {
        float t = 0.f;
#pragma unroll
        for (int w = 0; w < 8; w++) t += warp_s[w];
        atomicAdd(&g_loss, (double)t);
    }
}

// ---------------- single edge pass ------------------------------------------
__global__ void edge_pass(const int* __restrict__ ei) {
    int e = blockIdx.x * blockDim.x + threadIdx.x;
    if (e >= E_TOT) return;
    int s, d;
    if (e < N_EDGES) { s = ei[e]; d = ei[N_EDGES + e]; }
    else             { s = d = e - N_EDGES; }
    float x = g_a1s[s] + g_a1d[d];
    float sig = 1.0f / (1.0f + expf(-x));
    float ex = expf(sig);
    g_ew[e] = ex;
    atomicAdd(&g_den[d], ex);
    atomicAdd(&g_cnt[d], 1);
}

// ---------------- exclusive scan (shfl-based) -------------------------------
__global__ void scan_kernel() {
    __shared__ int wsum[32];
    int tid = threadIdx.x, lane = tid & 31, w = tid >> 5;
    int carry = 0;
    for (int base = 0; base < N_NODES; base += 1024) {
        int i = base + tid;
        int v = (i < N_NODES) ? g_cnt[i] : 0;
        int inc = v;
#pragma unroll
        for (int o = 1; o <= 16; o <<= 1) {
            int t = __shfl_up_sync(0xffffffffu, inc, o);
            if (lane >= o) inc += t;
        }
        if (lane == 31) wsum[w] = inc;
        __syncthreads();
        if (w == 0) {
            int s = wsum[lane];
#pragma unroll
            for (int o = 1; o <= 16; o <<= 1) {
                int t = __shfl_up_sync(0xffffffffu, s, o);
                if (lane >= o) s += t;
            }
            wsum[lane] = s;
        }
        __syncthreads();
        int off = (w > 0) ? wsum[w - 1] : 0;
        if (i < N_NODES) g_rowptr[i] = carry + off + inc - v;
        int tot = wsum[31];
        __syncthreads();
        carry += tot;
    }
    if (tid == 0) g_rowptr[N_NODES] = carry;
}

// ---------------- CSR fill --------------------------------------------------
__global__ void fill_kernel(const int* __restrict__ ei) {
    int e = blockIdx.x * blockDim.x + threadIdx.x;
    if (e >= E_TOT) return;
    int s, d;
    if (e < N_EDGES) { s = ei[e]; d = ei[N_EDGES + e]; }
    else             { s = d = e - N_EDGES; }
    int pos = atomicAdd(&g_fill[d], 1);
    int idx = g_rowptr[d] + pos;
    g_srcid[idx] = s;
    g_wn[idx] = g_ew[e] / g_den[d];
}

// ---------------- fused gather<0> + ELU + h2-normalize + xw3 ----------------
__global__ __launch_bounds__(256) void gather0_h2_kernel(const float* __restrict__ W2) {
    __shared__ float h1row[8][512];
    __shared__ float sh2[8][32];
    int gw = (blockIdx.x * blockDim.x + threadIdx.x) >> 5;
    if (gw >= N_NODES) return;
    int lane = threadIdx.x & 31;
    int w = threadIdx.x >> 5;
    int start = g_rowptr[gw], end = g_rowptr[gw + 1];

    const uint32_t* __restrict__ X = (const uint32_t*)g_xw1b;
    float acc[16];
#pragma unroll
    for (int q = 0; q < 16; q++) acc[q] = 0.f;

    for (int i = start; i < end; i++) {
        int s = g_srcid[i];
        float wgt = g_wn[i];
        const uint32_t* row = X + (size_t)s * (H1 / 2) + lane * 2;
#pragma unroll
        for (int seg = 0; seg < 4; seg++) {
            uint2 v = *(const uint2*)(row + seg * 64);
            acc[seg * 4 + 0] += wgt * bf_lo(v.x);
            acc[seg * 4 + 1] += wgt * bf_hi(v.x);
            acc[seg * 4 + 2] += wgt * bf_lo(v.y);
            acc[seg * 4 + 3] += wgt * bf_hi(v.y);
        }
    }
#pragma unroll
    for (int seg = 0; seg < 4; seg++) {
        float a0 = acc[seg * 4 + 0], a1 = acc[seg * 4 + 1];
        float a2 = acc[seg * 4 + 2], a3 = acc[seg * 4 + 3];
        a0 = (a0 > 0.f) ? a0 : expm1f(a0);
        a1 = (a1 > 0.f) ? a1 : expm1f(a1);
        a2 = (a2 > 0.f) ? a2 : expm1f(a2);
        a3 = (a3 > 0.f) ? a3 : expm1f(a3);
        *(float4*)&h1row[w][seg * 128 + lane * 4] = make_float4(a0, a1, a2, a3);
    }
    __syncwarp();

    float hj0 = 0.f, hj1 = 0.f;
    if (lane < H2) {
#pragma unroll 4
        for (int k = 0; k < H1; k += 2) {
            hj0 += h1row[w][k]     * W2[k * H2 + lane];
            hj1 += h1row[w][k + 1] * W2[(k + 1) * H2 + lane];
        }
    }
    float hj = hj0 + hj1;
    float sq = (lane < H2) ? hj * hj : 0.f;
#pragma unroll
    for (int o = 16; o; o >>= 1) sq += __shfl_xor_sync(0xffffffffu, sq, o);
    float inv = 1.0f / fmaxf(sqrtf(sq), 1e-12f);
    hj *= inv;
    if (lane < H2) sh2[w][lane] = hj;
    __syncwarp();

    __nv_bfloat16* outp = g_xw3b + (size_t)gw * H1;
    for (int k = lane; k < H1; k += 32) {
        float a = 0.f;
#pragma unroll
        for (int j = 0; j < H2; j++)
            a += sh2[w][j] * W2[k * H2 + j];
        outp[k] = __float2bfloat16(a);
    }
}

// ---------------- gather<1>: xw3b -> h3b (bf16) -----------------------------
__global__ __launch_bounds__(256) void gather1_kernel() {
    const uint32_t* __restrict__ X = (const uint32_t*)g_xw3b;
    int gw = (blockIdx.x * blockDim.x + threadIdx.x) >> 5;
    if (gw >= N_NODES) return;
    int lane = threadIdx.x & 31;
    int start = g_rowptr[gw], end = g_rowptr[gw + 1];

    float acc[16];
#pragma unroll
    for (int q = 0; q < 16; q++) acc[q] = 0.f;

    for (int i = start; i < end; i++) {
        int s = g_srcid[i];
        float wgt = g_wn[i];
        const uint32_t* row = X + (size_t)s * (H1 / 2) + lane * 2;
#pragma unroll
        for (int seg = 0; seg < 4; seg++) {
            uint2 v = *(const uint2*)(row + seg * 64);
            acc[seg * 4 + 0] += wgt * bf_lo(v.x);
            acc[seg * 4 + 1] += wgt * bf_hi(v.x);
            acc[seg * 4 + 2] += wgt * bf_lo(v.y);
            acc[seg * 4 + 3] += wgt * bf_hi(v.y);
        }
    }
#pragma unroll
    for (int seg = 0; seg < 4; seg++) {
        float a0 = acc[seg * 4 + 0], a1 = acc[seg * 4 + 1];
        float a2 = acc[seg * 4 + 2], a3 = acc[seg * 4 + 3];
        a0 = (a0 > 0.f) ? a0 : expm1f(a0);
        a1 = (a1 > 0.f) ? a1 : expm1f(a1);
        a2 = (a2 > 0.f) ? a2 : expm1f(a2);
        a3 = (a3 > 0.f) ? a3 : expm1f(a3);
        uint2* yr = (uint2*)(g_h3b + (size_t)gw * H1 + lane * 4 + seg * 128);
        *yr = make_uint2(pack_bf16x2(a0, a1), pack_bf16x2(a2, a3));
    }
}

// ---------------- finalize --------------------------------------------------
__global__ void finalize_kernel(float* out) {
    out[0] = (float)(g_loss / ((double)N_NODES * (double)N_FEAT));
}

// ---------------- launch ----------------------------------------------------
extern "C" void kernel_launch(void* const* d_in, const int* in_sizes, int n_in,
                              void* d_out, int out_size) {
    const float* features = (const float*)d_in[0];
    const int*   edge_idx = (const int*)d_in[1];
    const float* W1       = (const float*)d_in[2];
    const float* att_src1 = (const float*)d_in[3];
    const float* att_dst1 = (const float*)d_in[4];
    const float* W2       = (const float*)d_in[5];
    float* out = (float*)d_out;

    static bool attr_set = false;
    if (!attr_set) {
        cudaFuncSetAttribute(gemm4_kernel,
                             cudaFuncAttributeMaxDynamicSharedMemorySize, G4_DYN);
        attr_set = true;
    }

    init_kernel<<<(N_NODES + 255) / 256, 256>>>();

    convert_feat_kernel<<<2048, 256>>>(features);
    prep_w1_kernel<<<dim3(H1 / 32, N_FEAT / 32), dim3(32, 8)>>>(W1);

    // GEMM1: 64x128 tiles
    gemm1_kernel<<<dim3(H1 / 128, (N_NODES + 63) / 64), 256>>>(att_src1, att_dst1);

    int egrid = (E_TOT + 255) / 256;
    edge_pass<<<egrid, 256>>>(edge_idx);
    scan_kernel<<<1, 1024>>>();
    fill_kernel<<<egrid, 256>>>(edge_idx);

    gather0_h2_kernel<<<(N_NODES * 32 + 255) / 256, 256>>>(W2);

    gather1_kernel<<<(N_NODES * 32 + 255) / 256, 256>>>();

    // GEMM4 + fused MSE (dynamic smem, 3-stage)
    gemm4_kernel<<<dim3(N_FEAT / 128, (N_NODES + 127) / 128), 256, G4_DYN>>>();

    finalize_kernel<<<1, 1>>>(out);
}